// round 6
// baseline (speedup 1.0000x reference)
#include <cuda_runtime.h>
#include <cuda_bf16.h>
#include <cstdint>

#define DIM 256
#define BATCH 2
#define M_ROWS (BATCH * DIM * DIM)   // 131072
#define HID (4 * DIM)                // 1024
#define EPS_LN 1e-5f

// Scratch (no cudaMalloc). bf16 GEMM operands, pair-permuted k layout:
// element (row,k) at row*K + (k&~15) + pos*2 + (k&1), p=(k>>1)&7,
// pos = (p&3)*2 + (p>>2). Fragments then load as single LDS.64.
__device__ __align__(256) __nv_bfloat16 g_Y[(size_t)M_ROWS * DIM];
__device__ __align__(256) __nv_bfloat16 g_H[(size_t)M_ROWS * HID];
__device__ __align__(256) __nv_bfloat16 g_W1[(size_t)HID * DIM];
__device__ __align__(256) __nv_bfloat16 g_W2[(size_t)DIM * HID];

// ---------------------------------------------------------------------------
// helpers
// ---------------------------------------------------------------------------
__device__ __forceinline__ uint32_t smem_u32(const void* p) {
    uint32_t a;
    asm("{ .reg .u64 t; cvta.to.shared.u64 t, %1; cvt.u32.u64 %0, t; }"
        : "=r"(a) : "l"(p));
    return a;
}
__device__ __forceinline__ void cp16(uint32_t dst, const void* src) {
    asm volatile("cp.async.cg.shared.global [%0], [%1], 16;"
                 :: "r"(dst), "l"(src) : "memory");
}
__device__ __forceinline__ void cp_commit() {
    asm volatile("cp.async.commit_group;" ::: "memory");
}
template<int N> __device__ __forceinline__ void cp_wait() {
    asm volatile("cp.async.wait_group %0;" :: "n"(N) : "memory");
}
__device__ __forceinline__ void mma_bf16(float* c, uint32_t a0, uint32_t a1,
                                         uint32_t a2, uint32_t a3,
                                         uint32_t b0, uint32_t b1) {
    asm volatile(
        "mma.sync.aligned.m16n8k16.row.col.f32.bf16.bf16.f32 "
        "{%0,%1,%2,%3}, {%4,%5,%6,%7}, {%8,%9}, {%0,%1,%2,%3};"
        : "+f"(c[0]), "+f"(c[1]), "+f"(c[2]), "+f"(c[3])
        : "r"(a0), "r"(a1), "r"(a2), "r"(a3), "r"(b0), "r"(b1));
}
__device__ __forceinline__ float gelu_exact(float v) {
    return 0.5f * v * (1.f + erff(v * 0.70710678118654752f));
}
__device__ __forceinline__ int permpair(int k) {
    int p = (k >> 1) & 7;
    return (k & ~15) | (((((p & 3) << 1) | (p >> 2)) << 1) | (k & 1));
}

// ---------------------------------------------------------------------------
// weight prep: bf16 conversion + pair-permutation
// ---------------------------------------------------------------------------
__global__ void round_perm_bf16(const float* __restrict__ src,
                                __nv_bfloat16* __restrict__ dst, int n, int K) {
    int i = blockIdx.x * blockDim.x + threadIdx.x;
    if (i < n) {
        int row = i / K, k = i - row * K;
        dst[row * K + permpair(k)] = __float2bfloat16(src[i]);
    }
}

// ---------------------------------------------------------------------------
// Kernel 1: depthwise 7x7 conv + bias + LayerNorm over W (unchanged)
// ---------------------------------------------------------------------------
__global__ __launch_bounds__(128) void conv_ln_kernel(
    const float* __restrict__ x, const float* __restrict__ cw,
    const float* __restrict__ cb, const float* __restrict__ g,
    const float* __restrict__ bta, __nv_bfloat16* __restrict__ Y)
{
    __shared__ float s[10 * 262];
    __shared__ float swts[49];
    __shared__ float red[2][4][4];

    const int h0 = blockIdx.x * 4;
    const int c = blockIdx.y, b = blockIdx.z;
    const int tid = threadIdx.x;
    const int w0 = tid * 2;

    if (tid < 49) swts[tid] = cw[c * 49 + tid];

    const float* xp = x + ((size_t)(b * DIM + c)) * DIM * DIM;
    for (int i = tid; i < 10 * 262; i += 128) {
        int ro = i / 262, col = i - ro * 262;
        int hh = h0 - 3 + ro, ww = col - 3;
        float v = 0.f;
        if (hh >= 0 && hh < DIM && ww >= 0 && ww < DIM) v = xp[hh * DIM + ww];
        s[i] = v;
    }
    __syncthreads();

    float wr[49];
#pragma unroll
    for (int i = 0; i < 49; i++) wr[i] = swts[i];

    const float cbc = cb[c];
    float a0[4], a1[4];
#pragma unroll
    for (int r = 0; r < 4; r++) { a0[r] = cbc; a1[r] = cbc; }

#pragma unroll
    for (int ro = 0; ro < 10; ro++) {
        float2 p0 = *(const float2*)&s[ro * 262 + w0];
        float2 p1 = *(const float2*)&s[ro * 262 + w0 + 2];
        float2 p2 = *(const float2*)&s[ro * 262 + w0 + 4];
        float2 p3 = *(const float2*)&s[ro * 262 + w0 + 6];
        float v[8] = {p0.x, p0.y, p1.x, p1.y, p2.x, p2.y, p3.x, p3.y};
#pragma unroll
        for (int r = 0; r < 4; r++) {
            const int kh = ro - r;
            if (kh >= 0 && kh < 7) {
#pragma unroll
                for (int kw = 0; kw < 7; kw++) {
                    a0[r] += v[kw]     * wr[kh * 7 + kw];
                    a1[r] += v[kw + 1] * wr[kh * 7 + kw];
                }
            }
        }
    }

    const int lane = tid & 31, warp = tid >> 5;
#pragma unroll
    for (int r = 0; r < 4; r++) {
        float sv = a0[r] + a1[r];
        float sq = a0[r] * a0[r] + a1[r] * a1[r];
#pragma unroll
        for (int o = 16; o; o >>= 1) {
            sv += __shfl_xor_sync(0xffffffffu, sv, o);
            sq += __shfl_xor_sync(0xffffffffu, sq, o);
        }
        if (lane == 0) { red[0][r][warp] = sv; red[1][r][warp] = sq; }
    }
    __syncthreads();

    const float gv0 = g[w0], gv1 = g[w0 + 1];
    const float bv0 = bta[w0], bv1 = bta[w0 + 1];
    const size_t rowb = ((size_t)(b * DIM + c) * DIM + h0) * DIM;
    const int p = tid & 7, pos = ((p & 3) << 1) | (p >> 2);
    const int pw = (w0 & ~15) + pos * 2;
#pragma unroll
    for (int r = 0; r < 4; r++) {
        float S  = red[0][r][0] + red[0][r][1] + red[0][r][2] + red[0][r][3];
        float S2 = red[1][r][0] + red[1][r][1] + red[1][r][2] + red[1][r][3];
        float mu  = S * (1.f / 256.f);
        float var = S2 * (1.f / 256.f) - mu * mu;
        float inv = rsqrtf(var + EPS_LN);
        __nv_bfloat162 o;
        o.x = __float2bfloat16((a0[r] - mu) * inv * gv0 + bv0);
        o.y = __float2bfloat16((a1[r] - mu) * inv * gv1 + bv1);
        *(__nv_bfloat162*)&Y[rowb + (size_t)r * DIM + pw] = o;
    }
}

// ---------------------------------------------------------------------------
// bf16 m16n8k16 GEMM on pair-permuted operands.
// 128x128 CTA tile, 128 threads, 4 warps (2x2), warp tile 64x64.
// KC=32, 4-stage cp.async pipeline (16KB/stage).
// Per warp per k16-group: 16 LDS.64 -> 32 MMAs (2:1 MMA:LDS, high ILP).
// EPI==0: gelu(acc+bias) -> bf16 C [M,NOUT], pair-permuted n (= GEMM2 k)
// EPI==1: acc + bias + x -> fp32 transposed residual store out[b,n,c,h]
// ---------------------------------------------------------------------------
template<int K, int NOUT, int EPI>
__global__ void __launch_bounds__(128, 2) gemm_bf16(
    const __nv_bfloat16* __restrict__ A, const __nv_bfloat16* __restrict__ Bm,
    const float* __restrict__ bias, const float* __restrict__ xres, void* Cv)
{
    constexpr int KC = 32, NCH = K / KC;
    extern __shared__ char smem[];

    const int tid = threadIdx.x;
    const int m0 = blockIdx.y * 128, n0 = blockIdx.x * 128;

    // loader: thread tid owns full 64B k-slice of A row tid and B row tid
    const char* gA = (const char*)(A  + (size_t)(m0 + tid) * K);
    const char* gB = (const char*)(Bm + (size_t)(n0 + tid) * K);
    const uint32_t sb = smem_u32(smem);
    const uint32_t dA = sb + (uint32_t)tid * 32u;
    const uint32_t dB = dA + 8192u;

#define LOADST(s, kofs) do {                                                  \
    uint32_t oa_ = dA + (uint32_t)(s) * 16384u;                               \
    uint32_t ob_ = dB + (uint32_t)(s) * 16384u;                               \
    const char* pa_ = gA + (size_t)(kofs) * 2;                                \
    const char* pb_ = gB + (size_t)(kofs) * 2;                                \
    cp16(oa_,          pa_);      cp16(oa_ + 16u,          pa_ + 16);         \
    cp16(oa_ + 4096u,  pa_ + 32); cp16(oa_ + 4096u + 16u,  pa_ + 48);         \
    cp16(ob_,          pb_);      cp16(ob_ + 16u,          pb_ + 16);         \
    cp16(ob_ + 4096u,  pb_ + 32); cp16(ob_ + 4096u + 16u,  pb_ + 48);         \
    cp_commit();                                                              \
} while (0)

    const int warp = tid >> 5, lane = tid & 31;
    const int m_w = (warp >> 1) * 64, n_w = (warp & 1) * 64;
    const int r = lane >> 2, tig = lane & 3;
    const uint32_t aoff = (uint32_t)((m_w + r) * 32 + tig * 8);
    const uint32_t boff = 8192u + (uint32_t)((n_w + r) * 32 + tig * 8);

    float acc[4][8][4] = {};

    LOADST(0, 0); LOADST(1, KC); LOADST(2, 2 * KC);

#pragma unroll 1
    for (int it = 0; it < NCH; it++) {
        cp_wait<2>();
        __syncthreads();
        if (it + 3 < NCH) LOADST((it + 3) & 3, (it + 3) * KC);
        else cp_commit();   // keep group count exact for wait<2>

        const char* st = smem + (size_t)(it & 3) * 16384;
#pragma unroll
        for (int kg = 0; kg < 2; kg++) {
            const char* sk = st + kg * 4096;
            uint2 bf[8];
#pragma unroll
            for (int ni = 0; ni < 8; ni++)
                bf[ni] = *(const uint2*)(sk + boff + ni * 256);
#pragma unroll
            for (int mi = 0; mi < 4; mi++) {
                uint2 alo = *(const uint2*)(sk + aoff + mi * 512);
                uint2 ahi = *(const uint2*)(sk + aoff + mi * 512 + 256);
#pragma unroll
                for (int ni = 0; ni < 8; ni++)
                    mma_bf16(acc[mi][ni], alo.x, ahi.x, alo.y, ahi.y,
                             bf[ni].x, bf[ni].y);
            }
        }
    }
#undef LOADST

    // ------------------ epilogue ------------------
    if (EPI == 0) {
        __nv_bfloat16* C = (__nv_bfloat16*)Cv;
#pragma unroll
        for (int ni = 0; ni < 8; ni++) {
            const int n = n0 + n_w + ni * 8 + 2 * tig;
            const float bn0 = __ldg(bias + n), bn1 = __ldg(bias + n + 1);
            const int pp = (n >> 1) & 7;
            const int pw = (n & ~15) + ((((pp & 3) << 1) | (pp >> 2)) << 1);
#pragma unroll
            for (int mi = 0; mi < 4; mi++) {
                const size_t m = (size_t)(m0 + m_w + mi * 16 + r);
                __nv_bfloat162 v01, v23;
                v01.x = __float2bfloat16(gelu_exact(acc[mi][ni][0] + bn0));
                v01.y = __float2bfloat16(gelu_exact(acc[mi][ni][1] + bn1));
                v23.x = __float2bfloat16(gelu_exact(acc[mi][ni][2] + bn0));
                v23.y = __float2bfloat16(gelu_exact(acc[mi][ni][3] + bn1));
                *(__nv_bfloat162*)&C[m * NOUT + pw]       = v01;
                *(__nv_bfloat162*)&C[(m + 8) * NOUT + pw] = v23;
            }
        }
    } else {
        float* C = (float*)Cv;
        __syncthreads();
        float* tile = (float*)smem;
#pragma unroll
        for (int ni = 0; ni < 8; ni++) {
            const int n_l = n_w + ni * 8 + 2 * tig;
#pragma unroll
            for (int mi = 0; mi < 4; mi++) {
                const int m_l = m_w + mi * 16 + r;
                tile[n_l * 132 + m_l]           = acc[mi][ni][0];
                tile[(n_l + 1) * 132 + m_l]     = acc[mi][ni][1];
                tile[n_l * 132 + m_l + 8]       = acc[mi][ni][2];
                tile[(n_l + 1) * 132 + m_l + 8] = acc[mi][ni][3];
            }
        }
        __syncthreads();
        const int bb = m0 >> 16, cc = (m0 >> 8) & 255, h0 = m0 & 255;
#pragma unroll
        for (int itr = 0; itr < 32; itr++) {
            const int nl = warp + itr * 4;
            const float bj = __ldg(bias + n0 + nl);
            size_t base = ((size_t)bb << 24) + ((size_t)(n0 + nl) << 16)
                        + ((size_t)cc << 8) + (size_t)h0 + (size_t)(lane * 4);
            float4 t  = *(float4*)&tile[nl * 132 + lane * 4];
            float4 xv = *(const float4*)&xres[base];
            *(float4*)&C[base] = make_float4(t.x + bj + xv.x, t.y + bj + xv.y,
                                             t.z + bj + xv.z, t.w + bj + xv.w);
        }
    }
}

// ---------------------------------------------------------------------------
extern "C" void kernel_launch(void* const* d_in, const int* in_sizes, int n_in,
                              void* d_out, int out_size)
{
    (void)in_sizes; (void)n_in; (void)out_size;
    const float* x   = (const float*)d_in[0];
    const float* cw  = (const float*)d_in[1];
    const float* cb  = (const float*)d_in[2];
    const float* g   = (const float*)d_in[3];
    const float* bta = (const float*)d_in[4];
    const float* w1  = (const float*)d_in[5];
    const float* b1  = (const float*)d_in[6];
    const float* w2  = (const float*)d_in[7];
    const float* b2  = (const float*)d_in[8];
    float* out = (float*)d_out;

    __nv_bfloat16 *Y, *H, *W1, *W2;
    cudaGetSymbolAddress((void**)&Y,  g_Y);
    cudaGetSymbolAddress((void**)&H,  g_H);
    cudaGetSymbolAddress((void**)&W1, g_W1);
    cudaGetSymbolAddress((void**)&W2, g_W2);

    const int SMEM_BYTES = 69632;   // 4 stages x 16KB; EPI1 tile 67.6KB
    cudaFuncSetAttribute(gemm_bf16<DIM, HID, 0>,
                         cudaFuncAttributeMaxDynamicSharedMemorySize, SMEM_BYTES);
    cudaFuncSetAttribute(gemm_bf16<HID, DIM, 1>,
                         cudaFuncAttributeMaxDynamicSharedMemorySize, SMEM_BYTES);

    // 0) weights -> bf16 + pair-permuted scratch
    round_perm_bf16<<<(HID * DIM + 255) / 256, 256>>>(w1, W1, HID * DIM, DIM);
    round_perm_bf16<<<(DIM * HID + 255) / 256, 256>>>(w2, W2, DIM * HID, HID);

    // 1) depthwise conv + bias + LayerNorm(W) -> Y (bf16, permuted)
    conv_ln_kernel<<<dim3(DIM / 4, DIM, BATCH), 128>>>(x, cw, cb, g, bta, Y);

    // 2) GEMM1 (K=256 -> N=1024) + bias + exact GELU -> H (bf16, permuted)
    gemm_bf16<DIM, HID, 0><<<dim3(HID / 128, M_ROWS / 128), 128, SMEM_BYTES>>>(
        Y, W1, b1, nullptr, H);

    // 3) GEMM2 (K=1024 -> N=256) + bias + transposed residual -> out (fp32)
    gemm_bf16<HID, DIM, 1><<<dim3(DIM / 128, M_ROWS / 128), 128, SMEM_BYTES>>>(
        H, W2, b2, x, out);
}

// round 9
// speedup vs baseline: 1.1141x; 1.1141x over previous
#include <cuda_runtime.h>
#include <cuda_bf16.h>
#include <cstdint>

#define DIM 256
#define BATCH 2
#define M_ROWS (BATCH * DIM * DIM)   // 131072
#define HID (4 * DIM)                // 1024
#define EPS_LN 1e-5f

// Scratch (no cudaMalloc). bf16 GEMM operands, pair-permuted k layout:
// element (row,k) at row*K + (k&~15) + pos*2 + (k&1), p=(k>>1)&7,
// pos = (p&3)*2 + (p>>2). Fragments then load as single LDS.64.
__device__ __align__(256) __nv_bfloat16 g_Y[(size_t)M_ROWS * DIM];
__device__ __align__(256) __nv_bfloat16 g_H[(size_t)M_ROWS * HID];
__device__ __align__(256) __nv_bfloat16 g_W1[(size_t)HID * DIM];
__device__ __align__(256) __nv_bfloat16 g_W2[(size_t)DIM * HID];

// ---------------------------------------------------------------------------
// helpers
// ---------------------------------------------------------------------------
__device__ __forceinline__ uint32_t smem_u32(const void* p) {
    uint32_t a;
    asm("{ .reg .u64 t; cvta.to.shared.u64 t, %1; cvt.u32.u64 %0, t; }"
        : "=r"(a) : "l"(p));
    return a;
}
__device__ __forceinline__ void cp16(uint32_t dst, const void* src) {
    asm volatile("cp.async.cg.shared.global [%0], [%1], 16;"
                 :: "r"(dst), "l"(src) : "memory");
}
__device__ __forceinline__ void cp_commit() {
    asm volatile("cp.async.commit_group;" ::: "memory");
}
template<int N> __device__ __forceinline__ void cp_wait() {
    asm volatile("cp.async.wait_group %0;" :: "n"(N) : "memory");
}
__device__ __forceinline__ void mma_bf16(float* c, uint32_t a0, uint32_t a1,
                                         uint32_t a2, uint32_t a3,
                                         uint32_t b0, uint32_t b1) {
    asm volatile(
        "mma.sync.aligned.m16n8k16.row.col.f32.bf16.bf16.f32 "
        "{%0,%1,%2,%3}, {%4,%5,%6,%7}, {%8,%9}, {%0,%1,%2,%3};"
        : "+f"(c[0]), "+f"(c[1]), "+f"(c[2]), "+f"(c[3])
        : "r"(a0), "r"(a1), "r"(a2), "r"(a3), "r"(b0), "r"(b1));
}
__device__ __forceinline__ float gelu_exact(float v) {
    return 0.5f * v * (1.f + erff(v * 0.70710678118654752f));
}
__device__ __forceinline__ int permpair(int k) {
    int p = (k >> 1) & 7;
    return (k & ~15) | (((((p & 3) << 1) | (p >> 2)) << 1) | (k & 1));
}

// ---------------------------------------------------------------------------
// weight prep: bf16 conversion + pair-permutation
// ---------------------------------------------------------------------------
__global__ void round_perm_bf16(const float* __restrict__ src,
                                __nv_bfloat16* __restrict__ dst, int n, int K) {
    int i = blockIdx.x * blockDim.x + threadIdx.x;
    if (i < n) {
        int row = i / K, k = i - row * K;
        dst[row * K + permpair(k)] = __float2bfloat16(src[i]);
    }
}

// ---------------------------------------------------------------------------
// Kernel 1: depthwise 7x7 conv + bias + LayerNorm over W (unchanged)
// ---------------------------------------------------------------------------
__global__ __launch_bounds__(128) void conv_ln_kernel(
    const float* __restrict__ x, const float* __restrict__ cw,
    const float* __restrict__ cb, const float* __restrict__ g,
    const float* __restrict__ bta, __nv_bfloat16* __restrict__ Y)
{
    __shared__ float s[10 * 262];
    __shared__ float swts[49];
    __shared__ float red[2][4][4];

    const int h0 = blockIdx.x * 4;
    const int c = blockIdx.y, b = blockIdx.z;
    const int tid = threadIdx.x;
    const int w0 = tid * 2;

    if (tid < 49) swts[tid] = cw[c * 49 + tid];

    const float* xp = x + ((size_t)(b * DIM + c)) * DIM * DIM;
    for (int i = tid; i < 10 * 262; i += 128) {
        int ro = i / 262, col = i - ro * 262;
        int hh = h0 - 3 + ro, ww = col - 3;
        float v = 0.f;
        if (hh >= 0 && hh < DIM && ww >= 0 && ww < DIM) v = xp[hh * DIM + ww];
        s[i] = v;
    }
    __syncthreads();

    float wr[49];
#pragma unroll
    for (int i = 0; i < 49; i++) wr[i] = swts[i];

    const float cbc = cb[c];
    float a0[4], a1[4];
#pragma unroll
    for (int r = 0; r < 4; r++) { a0[r] = cbc; a1[r] = cbc; }

#pragma unroll
    for (int ro = 0; ro < 10; ro++) {
        float2 p0 = *(const float2*)&s[ro * 262 + w0];
        float2 p1 = *(const float2*)&s[ro * 262 + w0 + 2];
        float2 p2 = *(const float2*)&s[ro * 262 + w0 + 4];
        float2 p3 = *(const float2*)&s[ro * 262 + w0 + 6];
        float v[8] = {p0.x, p0.y, p1.x, p1.y, p2.x, p2.y, p3.x, p3.y};
#pragma unroll
        for (int r = 0; r < 4; r++) {
            const int kh = ro - r;
            if (kh >= 0 && kh < 7) {
#pragma unroll
                for (int kw = 0; kw < 7; kw++) {
                    a0[r] += v[kw]     * wr[kh * 7 + kw];
                    a1[r] += v[kw + 1] * wr[kh * 7 + kw];
                }
            }
        }
    }

    const int lane = tid & 31, warp = tid >> 5;
#pragma unroll
    for (int r = 0; r < 4; r++) {
        float sv = a0[r] + a1[r];
        float sq = a0[r] * a0[r] + a1[r] * a1[r];
#pragma unroll
        for (int o = 16; o; o >>= 1) {
            sv += __shfl_xor_sync(0xffffffffu, sv, o);
            sq += __shfl_xor_sync(0xffffffffu, sq, o);
        }
        if (lane == 0) { red[0][r][warp] = sv; red[1][r][warp] = sq; }
    }
    __syncthreads();

    const float gv0 = g[w0], gv1 = g[w0 + 1];
    const float bv0 = bta[w0], bv1 = bta[w0 + 1];
    const size_t rowb = ((size_t)(b * DIM + c) * DIM + h0) * DIM;
    const int p = tid & 7, pos = ((p & 3) << 1) | (p >> 2);
    const int pw = (w0 & ~15) + pos * 2;
#pragma unroll
    for (int r = 0; r < 4; r++) {
        float S  = red[0][r][0] + red[0][r][1] + red[0][r][2] + red[0][r][3];
        float S2 = red[1][r][0] + red[1][r][1] + red[1][r][2] + red[1][r][3];
        float mu  = S * (1.f / 256.f);
        float var = S2 * (1.f / 256.f) - mu * mu;
        float inv = rsqrtf(var + EPS_LN);
        __nv_bfloat162 o;
        o.x = __float2bfloat16((a0[r] - mu) * inv * gv0 + bv0);
        o.y = __float2bfloat16((a1[r] - mu) * inv * gv1 + bv1);
        *(__nv_bfloat162*)&Y[rowb + (size_t)r * DIM + pw] = o;
    }
}

// ---------------------------------------------------------------------------
// GEMM1 persistent: H = gelu(Y @ W1^T + b1), K=256, N=1024.
// 296 CTAs (= 2/SM x 148, one wave): 8 n-panels x 37 m-groups.
// W1 panel (128 x 256 bf16 = 64KB) resident in SMEM, loaded once (full 32B
// per row per kg-slab!) and fenced with its own wait+sync. A streams through
// a 4-stage x 8KB cp.async pipeline running continuously across m-tiles.
// ---------------------------------------------------------------------------
__global__ void __launch_bounds__(128, 2) gemm1_persist(
    const __nv_bfloat16* __restrict__ A, const __nv_bfloat16* __restrict__ Bm,
    const float* __restrict__ bias, __nv_bfloat16* __restrict__ C)
{
    constexpr int K = DIM, NOUT = HID, NGR = 37;
    extern __shared__ char smem[];
    // byte offsets inside smem[]: B panel [0, 65536), A stages [65536, 98304)
    const uint32_t sb = smem_u32(smem);

    const int tid = threadIdx.x;
    const int panel = blockIdx.x & 7;
    const int gr = blockIdx.x >> 3;               // 0..36
    const int t0 = (gr * 1024) / NGR, t1 = ((gr + 1) * 1024) / NGR;
    const int n0 = panel * 128;

    // ---- resident B panel: row tid (512B = 16 kg x 32B) -> 16 slabs of 4KB.
    // BUGFIX vs r7/r8: copy the FULL 32 bytes per kg-slab (two cp16).
    {
        const char* gB = (const char*)(Bm + (size_t)(n0 + tid) * K);
        const uint32_t db = sb + (uint32_t)tid * 32u;
#pragma unroll
        for (int kg = 0; kg < 16; kg++) {
            cp16(db + (uint32_t)kg * 4096u,       gB + kg * 32);
            cp16(db + (uint32_t)kg * 4096u + 16u, gB + kg * 32 + 16);
        }
        cp_commit();
        cp_wait<0>();
        __syncthreads();   // B panel fully resident; group count back to 0
    }

    // ---- A stage prefetch: stage s, m-tile t, k-chunk j (KC=32) ----
    const char* gAr = (const char*)A + (size_t)tid * (K * 2);
    const uint32_t dA = sb + 65536u + (uint32_t)tid * 32u;
#define LOADA(s, t, j) do {                                                   \
    const char* pa_ = gAr + (size_t)(t) * (128 * K * 2) + (size_t)(j) * 64;   \
    uint32_t da_ = dA + (uint32_t)(s) * 8192u;                                \
    cp16(da_, pa_);              cp16(da_ + 16u, pa_ + 16);                   \
    cp16(da_ + 4096u, pa_ + 32); cp16(da_ + 4096u + 16u, pa_ + 48);           \
    cp_commit();                                                              \
} while (0)

    const int warp = tid >> 5, lane = tid & 31;
    const int m_w = (warp >> 1) * 64, n_w = (warp & 1) * 64;
    const int r = lane >> 2, tig = lane & 3;
    const int aoff = 65536 + (m_w + r) * 32 + tig * 8;   // + stage*8192 + kg*4096 + mi*512
    const int boff = (n_w + r) * 32 + tig * 8;           // + kgglobal*4096

    const int total = (t1 - t0) * 8;
    LOADA(0, t0, 0); LOADA(1, t0, 1); LOADA(2, t0, 2);

    int L = 0;
#pragma unroll 1
    for (int t = t0; t < t1; t++) {
        float acc[4][8][4] = {};
#pragma unroll 1
        for (int j = 0; j < 8; j++, L++) {
            cp_wait<2>();
            __syncthreads();
            const int Lp = L + 3;
            if (Lp < total) LOADA(Lp & 3, t0 + (Lp >> 3), Lp & 7);
            else cp_commit();   // keep group count exact for wait<2>

            const char* sa = smem + aoff + (L & 3) * 8192;
            const char* sbp = smem + boff + j * 8192;    // kg pair (2j, 2j+1)
#pragma unroll
            for (int kg = 0; kg < 2; kg++) {
                const char* sk = sa + kg * 4096;
                const char* bk = sbp + kg * 4096;
                uint2 bf[8];
#pragma unroll
                for (int ni = 0; ni < 8; ni++)
                    bf[ni] = *(const uint2*)(bk + ni * 256);
#pragma unroll
                for (int mi = 0; mi < 4; mi++) {
                    uint2 alo = *(const uint2*)(sk + mi * 512);
                    uint2 ahi = *(const uint2*)(sk + mi * 512 + 256);
#pragma unroll
                    for (int ni = 0; ni < 8; ni++)
                        mma_bf16(acc[mi][ni], alo.x, ahi.x, alo.y, ahi.y,
                                 bf[ni].x, bf[ni].y);
                }
            }
        }

        // epilogue for tile t (registers + global only; prefetch in flight)
        const int m0 = t * 128;
#pragma unroll
        for (int ni = 0; ni < 8; ni++) {
            const int n = n0 + n_w + ni * 8 + 2 * tig;
            const float bn0 = __ldg(bias + n), bn1 = __ldg(bias + n + 1);
            const int pp = (n >> 1) & 7;
            const int pw = (n & ~15) + ((((pp & 3) << 1) | (pp >> 2)) << 1);
#pragma unroll
            for (int mi = 0; mi < 4; mi++) {
                const size_t m = (size_t)(m0 + m_w + mi * 16 + r);
                __nv_bfloat162 v01, v23;
                v01.x = __float2bfloat16(gelu_exact(acc[mi][ni][0] + bn0));
                v01.y = __float2bfloat16(gelu_exact(acc[mi][ni][1] + bn1));
                v23.x = __float2bfloat16(gelu_exact(acc[mi][ni][2] + bn0));
                v23.y = __float2bfloat16(gelu_exact(acc[mi][ni][3] + bn1));
                *(__nv_bfloat162*)&C[m * NOUT + pw]       = v01;
                *(__nv_bfloat162*)&C[(m + 8) * NOUT + pw] = v23;
            }
        }
    }
#undef LOADA
}

// ---------------------------------------------------------------------------
// GEMM2 (unchanged, proven): bf16 m16n8k16, 128x128 tile, 128 threads,
// 4-stage pipeline. acc + bias + x -> fp32 transposed residual out[b,n,c,h].
// ---------------------------------------------------------------------------
__global__ void __launch_bounds__(128, 2) gemm2_bf16(
    const __nv_bfloat16* __restrict__ A, const __nv_bfloat16* __restrict__ Bm,
    const float* __restrict__ bias, const float* __restrict__ xres,
    float* __restrict__ C)
{
    constexpr int K = HID, KC = 32, NCH = K / KC;
    extern __shared__ char smem[];

    const int tid = threadIdx.x;
    const int m0 = blockIdx.y * 128, n0 = blockIdx.x * 128;

    const char* gA = (const char*)(A  + (size_t)(m0 + tid) * K);
    const char* gB = (const char*)(Bm + (size_t)(n0 + tid) * K);
    const uint32_t sb = smem_u32(smem);
    const uint32_t dA = sb + (uint32_t)tid * 32u;
    const uint32_t dB = dA + 8192u;

#define LOADST(s, kofs) do {                                                  \
    uint32_t oa_ = dA + (uint32_t)(s) * 16384u;                               \
    uint32_t ob_ = dB + (uint32_t)(s) * 16384u;                               \
    const char* pa_ = gA + (size_t)(kofs) * 2;                                \
    const char* pb_ = gB + (size_t)(kofs) * 2;                                \
    cp16(oa_,          pa_);      cp16(oa_ + 16u,          pa_ + 16);         \
    cp16(oa_ + 4096u,  pa_ + 32); cp16(oa_ + 4096u + 16u,  pa_ + 48);         \
    cp16(ob_,          pb_);      cp16(ob_ + 16u,          pb_ + 16);         \
    cp16(ob_ + 4096u,  pb_ + 32); cp16(ob_ + 4096u + 16u,  pb_ + 48);         \
    cp_commit();                                                              \
} while (0)

    const int warp = tid >> 5, lane = tid & 31;
    const int m_w = (warp >> 1) * 64, n_w = (warp & 1) * 64;
    const int r = lane >> 2, tig = lane & 3;
    const uint32_t aoff = (uint32_t)((m_w + r) * 32 + tig * 8);
    const uint32_t boff = 8192u + (uint32_t)((n_w + r) * 32 + tig * 8);

    float acc[4][8][4] = {};

    LOADST(0, 0); LOADST(1, KC); LOADST(2, 2 * KC);

#pragma unroll 1
    for (int it = 0; it < NCH; it++) {
        cp_wait<2>();
        __syncthreads();
        if (it + 3 < NCH) LOADST((it + 3) & 3, (it + 3) * KC);
        else cp_commit();

        const char* st = smem + (size_t)(it & 3) * 16384;
#pragma unroll
        for (int kg = 0; kg < 2; kg++) {
            const char* sk = st + kg * 4096;
            uint2 bf[8];
#pragma unroll
            for (int ni = 0; ni < 8; ni++)
                bf[ni] = *(const uint2*)(sk + boff + ni * 256);
#pragma unroll
            for (int mi = 0; mi < 4; mi++) {
                uint2 alo = *(const uint2*)(sk + aoff + mi * 512);
                uint2 ahi = *(const uint2*)(sk + aoff + mi * 512 + 256);
#pragma unroll
                for (int ni = 0; ni < 8; ni++)
                    mma_bf16(acc[mi][ni], alo.x, ahi.x, alo.y, ahi.y,
                             bf[ni].x, bf[ni].y);
            }
        }
    }
#undef LOADST

    __syncthreads();
    float* tile = (float*)smem;
#pragma unroll
    for (int ni = 0; ni < 8; ni++) {
        const int n_l = n_w + ni * 8 + 2 * tig;
#pragma unroll
        for (int mi = 0; mi < 4; mi++) {
            const int m_l = m_w + mi * 16 + r;
            tile[n_l * 132 + m_l]           = acc[mi][ni][0];
            tile[(n_l + 1) * 132 + m_l]     = acc[mi][ni][1];
            tile[n_l * 132 + m_l + 8]       = acc[mi][ni][2];
            tile[(n_l + 1) * 132 + m_l + 8] = acc[mi][ni][3];
        }
    }
    __syncthreads();
    const int bb = m0 >> 16, cc = (m0 >> 8) & 255, h0 = m0 & 255;
#pragma unroll
    for (int itr = 0; itr < 32; itr++) {
        const int nl = warp + itr * 4;
        const float bj = __ldg(bias + n0 + nl);
        size_t base = ((size_t)bb << 24) + ((size_t)(n0 + nl) << 16)
                    + ((size_t)cc << 8) + (size_t)h0 + (size_t)(lane * 4);
        float4 t  = *(float4*)&tile[nl * 132 + lane * 4];
        float4 xv = *(const float4*)&xres[base];
        *(float4*)&C[base] = make_float4(t.x + bj + xv.x, t.y + bj + xv.y,
                                         t.z + bj + xv.z, t.w + bj + xv.w);
    }
}

// ---------------------------------------------------------------------------
extern "C" void kernel_launch(void* const* d_in, const int* in_sizes, int n_in,
                              void* d_out, int out_size)
{
    (void)in_sizes; (void)n_in; (void)out_size;
    const float* x   = (const float*)d_in[0];
    const float* cw  = (const float*)d_in[1];
    const float* cb  = (const float*)d_in[2];
    const float* g   = (const float*)d_in[3];
    const float* bta = (const float*)d_in[4];
    const float* w1  = (const float*)d_in[5];
    const float* b1  = (const float*)d_in[6];
    const float* w2  = (const float*)d_in[7];
    const float* b2  = (const float*)d_in[8];
    float* out = (float*)d_out;

    __nv_bfloat16 *Y, *H, *W1, *W2;
    cudaGetSymbolAddress((void**)&Y,  g_Y);
    cudaGetSymbolAddress((void**)&H,  g_H);
    cudaGetSymbolAddress((void**)&W1, g_W1);
    cudaGetSymbolAddress((void**)&W2, g_W2);

    const int SMEM_G1 = 98304;   // 64KB B panel + 4 x 8KB A stages
    const int SMEM_G2 = 69632;   // 4 x 16KB stages; 67.6KB transpose tile
    cudaFuncSetAttribute(gemm1_persist,
                         cudaFuncAttributeMaxDynamicSharedMemorySize, SMEM_G1);
    cudaFuncSetAttribute(gemm2_bf16,
                         cudaFuncAttributeMaxDynamicSharedMemorySize, SMEM_G2);

    // 0) weights -> bf16 + pair-permuted scratch
    round_perm_bf16<<<(HID * DIM + 255) / 256, 256>>>(w1, W1, HID * DIM, DIM);
    round_perm_bf16<<<(DIM * HID + 255) / 256, 256>>>(w2, W2, DIM * HID, HID);

    // 1) depthwise conv + bias + LayerNorm(W) -> Y (bf16, permuted)
    conv_ln_kernel<<<dim3(DIM / 4, DIM, BATCH), 128>>>(x, cw, cb, g, bta, Y);

    // 2) GEMM1 persistent (K=256 -> N=1024) + bias + exact GELU -> H
    gemm1_persist<<<296, 128, SMEM_G1>>>(Y, W1, b1, H);

    // 3) GEMM2 (K=1024 -> N=256) + bias + transposed residual -> out (fp32)
    gemm2_bf16<<<dim3(DIM / 128, M_ROWS / 128), 128, SMEM_G2>>>(
        H, W2, b2, x, out);
}

// round 10
// speedup vs baseline: 1.6139x; 1.4487x over previous
#include <cuda_runtime.h>
#include <cuda_bf16.h>
#include <cstdint>

#define DIM 256
#define BATCH 2
#define M_ROWS (BATCH * DIM * DIM)   // 131072
#define HID (4 * DIM)                // 1024
#define EPS_LN 1e-5f

// Scratch. GEMM operands in TILE-BLOCK layout: 16KB block = (128 rows x 64 k)
// = 4 kg-slabs of 4KB; slab = row*32B; within 32B: 8 bf16-pairs at permuted
// position pos(p)=((p&3)<<1)|(p>>2), p=(k>>1)&7. Blocks are contiguous so a
// whole stage loads with ONE cp.async.bulk.
//   Y  blocks: (m-tile t)*4  + (k>>6)            [GEMM1 A, K=256]
//   H  blocks: (m-tile t)*16 + (k>>6)            [GEMM2 A, K=1024]
//   W1 panels: panel p = 64KB contiguous (slab = k>>4, 16 slabs)
//   W2 blocks: (panel p)*16 + (k>>6)
__device__ __align__(256) __nv_bfloat16 g_Y[(size_t)M_ROWS * DIM];
__device__ __align__(256) __nv_bfloat16 g_H[(size_t)M_ROWS * HID];
__device__ __align__(256) __nv_bfloat16 g_W1[(size_t)HID * DIM];
__device__ __align__(256) __nv_bfloat16 g_W2[(size_t)DIM * HID];

// ---------------------------------------------------------------------------
// helpers
// ---------------------------------------------------------------------------
__device__ __forceinline__ uint32_t smem_u32(const void* p) {
    uint32_t a;
    asm("{ .reg .u64 t; cvta.to.shared.u64 t, %1; cvt.u32.u64 %0, t; }"
        : "=r"(a) : "l"(p));
    return a;
}
__device__ __forceinline__ void mbar_init(uint32_t a, uint32_t cnt) {
    asm volatile("mbarrier.init.shared.b64 [%0], %1;" :: "r"(a), "r"(cnt) : "memory");
}
__device__ __forceinline__ void mbar_expect(uint32_t a, uint32_t tx) {
    asm volatile("mbarrier.arrive.expect_tx.shared.b64 _, [%0], %1;"
                 :: "r"(a), "r"(tx) : "memory");
}
__device__ __forceinline__ void mbar_arrive(uint32_t a) {
    asm volatile("mbarrier.arrive.shared.b64 _, [%0];" :: "r"(a) : "memory");
}
__device__ __forceinline__ void mbar_wait(uint32_t a, uint32_t parity) {
    asm volatile(
        "{\n\t.reg .pred P;\n\t"
        "W_%=:\n\t"
        "mbarrier.try_wait.parity.shared.b64 P, [%0], %1, 0x989680;\n\t"
        "@!P bra W_%=;\n\t}"
        :: "r"(a), "r"(parity) : "memory");
}
__device__ __forceinline__ void cpbulk(uint32_t dst, const void* src,
                                       uint32_t bytes, uint32_t mbar) {
    asm volatile(
        "cp.async.bulk.shared::cluster.global.mbarrier::complete_tx::bytes "
        "[%0], [%1], %2, [%3];"
        :: "r"(dst), "l"(src), "r"(bytes), "r"(mbar) : "memory");
}
__device__ __forceinline__ void mma_bf16(float* c, uint32_t a0, uint32_t a1,
                                         uint32_t a2, uint32_t a3,
                                         uint32_t b0, uint32_t b1) {
    asm volatile(
        "mma.sync.aligned.m16n8k16.row.col.f32.bf16.bf16.f32 "
        "{%0,%1,%2,%3}, {%4,%5,%6,%7}, {%8,%9}, {%0,%1,%2,%3};"
        : "+f"(c[0]), "+f"(c[1]), "+f"(c[2]), "+f"(c[3])
        : "r"(a0), "r"(a1), "r"(a2), "r"(a3), "r"(b0), "r"(b1));
}
__device__ __forceinline__ float gelu_exact(float v) {
    return 0.5f * v * (1.f + erff(v * 0.70710678118654752f));
}

// ---------------------------------------------------------------------------
// weight prep
// ---------------------------------------------------------------------------
__global__ void prep_w1(const float* __restrict__ src, __nv_bfloat16* __restrict__ dst) {
    int i = blockIdx.x * blockDim.x + threadIdx.x;
    if (i < HID * DIM) {
        int n = i / DIM, k = i - n * DIM;
        int p = (k >> 1) & 7, pos = ((p & 3) << 1) | (p >> 2);
        size_t byte = (size_t)(n >> 7) * 65536 + (size_t)(k >> 4) * 4096
                    + (size_t)(n & 127) * 32 + pos * 4 + (k & 1) * 2;
        *(__nv_bfloat16*)((char*)dst + byte) = __float2bfloat16(src[i]);
    }
}
__global__ void prep_w2(const float* __restrict__ src, __nv_bfloat16* __restrict__ dst) {
    int i = blockIdx.x * blockDim.x + threadIdx.x;
    if (i < DIM * HID) {
        int n = i / HID, k = i - n * HID;
        int p = (k >> 1) & 7, pos = ((p & 3) << 1) | (p >> 2);
        size_t byte = (size_t)((n >> 7) * 16 + (k >> 6)) * 16384
                    + (size_t)((k >> 4) & 3) * 4096
                    + (size_t)(n & 127) * 32 + pos * 4 + (k & 1) * 2;
        *(__nv_bfloat16*)((char*)dst + byte) = __float2bfloat16(src[i]);
    }
}

// ---------------------------------------------------------------------------
// Kernel 1: depthwise 7x7 conv + bias + LayerNorm over W.
// Same compute as R9; stores Y in tile-block layout (k = w).
// ---------------------------------------------------------------------------
__global__ __launch_bounds__(128) void conv_ln_kernel(
    const float* __restrict__ x, const float* __restrict__ cw,
    const float* __restrict__ cb, const float* __restrict__ g,
    const float* __restrict__ bta, __nv_bfloat16* __restrict__ Y)
{
    __shared__ float s[10 * 262];
    __shared__ float swts[49];
    __shared__ float red[2][4][4];

    const int h0 = blockIdx.x * 4;
    const int c = blockIdx.y, b = blockIdx.z;
    const int tid = threadIdx.x;
    const int w0 = tid * 2;

    if (tid < 49) swts[tid] = cw[c * 49 + tid];

    const float* xp = x + ((size_t)(b * DIM + c)) * DIM * DIM;
    for (int i = tid; i < 10 * 262; i += 128) {
        int ro = i / 262, col = i - ro * 262;
        int hh = h0 - 3 + ro, ww = col - 3;
        float v = 0.f;
        if (hh >= 0 && hh < DIM && ww >= 0 && ww < DIM) v = xp[hh * DIM + ww];
        s[i] = v;
    }
    __syncthreads();

    float wr[49];
#pragma unroll
    for (int i = 0; i < 49; i++) wr[i] = swts[i];

    const float cbc = cb[c];
    float a0[4], a1[4];
#pragma unroll
    for (int r = 0; r < 4; r++) { a0[r] = cbc; a1[r] = cbc; }

#pragma unroll
    for (int ro = 0; ro < 10; ro++) {
        float2 p0 = *(const float2*)&s[ro * 262 + w0];
        float2 p1 = *(const float2*)&s[ro * 262 + w0 + 2];
        float2 p2 = *(const float2*)&s[ro * 262 + w0 + 4];
        float2 p3 = *(const float2*)&s[ro * 262 + w0 + 6];
        float v[8] = {p0.x, p0.y, p1.x, p1.y, p2.x, p2.y, p3.x, p3.y};
#pragma unroll
        for (int r = 0; r < 4; r++) {
            const int kh = ro - r;
            if (kh >= 0 && kh < 7) {
#pragma unroll
                for (int kw = 0; kw < 7; kw++) {
                    a0[r] += v[kw]     * wr[kh * 7 + kw];
                    a1[r] += v[kw + 1] * wr[kh * 7 + kw];
                }
            }
        }
    }

    const int lane = tid & 31, warp = tid >> 5;
#pragma unroll
    for (int r = 0; r < 4; r++) {
        float sv = a0[r] + a1[r];
        float sq = a0[r] * a0[r] + a1[r] * a1[r];
#pragma unroll
        for (int o = 16; o; o >>= 1) {
            sv += __shfl_xor_sync(0xffffffffu, sv, o);
            sq += __shfl_xor_sync(0xffffffffu, sq, o);
        }
        if (lane == 0) { red[0][r][warp] = sv; red[1][r][warp] = sq; }
    }
    __syncthreads();

    const float gv0 = g[w0], gv1 = g[w0 + 1];
    const float bv0 = bta[w0], bv1 = bta[w0 + 1];
    const int p = tid & 7, pos = ((p & 3) << 1) | (p >> 2);
    const int j = w0 >> 6, kgl = (w0 >> 4) & 3;
    const size_t mbase = (size_t)(b * DIM + c) * DIM;
#pragma unroll
    for (int r = 0; r < 4; r++) {
        float S  = red[0][r][0] + red[0][r][1] + red[0][r][2] + red[0][r][3];
        float S2 = red[1][r][0] + red[1][r][1] + red[1][r][2] + red[1][r][3];
        float mu  = S * (1.f / 256.f);
        float var = S2 * (1.f / 256.f) - mu * mu;
        float inv = rsqrtf(var + EPS_LN);
        __nv_bfloat162 o;
        o.x = __float2bfloat16((a0[r] - mu) * inv * gv0 + bv0);
        o.y = __float2bfloat16((a1[r] - mu) * inv * gv1 + bv1);
        const size_t m = mbase + h0 + r;
        const size_t byte = (size_t)((m >> 7) * 4 + j) * 16384
                          + kgl * 4096 + (m & 127) * 32 + pos * 4;
        *(__nv_bfloat162*)((char*)Y + byte) = o;
    }
}

// ---------------------------------------------------------------------------
// GEMM1 persistent: H = gelu(Y @ W1^T + b1). 296 CTAs (8 panels x 37 groups).
// Resident 64KB W1 panel (1 bulk) + 3 x 16KB A stages (1 bulk each, KC=64).
// mbarrier full(cnt 1,tx)/empty(cnt 128) pipeline, producer = tid 0.
// Epilogue writes H in GEMM2 tile-block layout.
// ---------------------------------------------------------------------------
__global__ void __launch_bounds__(128, 2) gemm1_persist(
    const __nv_bfloat16* __restrict__ A, const __nv_bfloat16* __restrict__ Bm,
    const float* __restrict__ bias, __nv_bfloat16* __restrict__ C)
{
    constexpr int NGR = 37;
    extern __shared__ char smem[];          // [0,64K) panel, [64K,112K) stages
    __shared__ uint64_t mbar[7];            // full0..2, empty0..2, panel
    const uint32_t sb = smem_u32(smem);
    const uint32_t mb = smem_u32(mbar);

    const int tid = threadIdx.x;
    const int panel = blockIdx.x & 7;
    const int gr = blockIdx.x >> 3;
    const int t0 = (gr * 1024) / NGR, t1 = ((gr + 1) * 1024) / NGR;
    const int n0 = panel * 128;
    const int total = (t1 - t0) * 4;

    if (tid == 0) {
#pragma unroll
        for (int s = 0; s < 3; s++) {
            mbar_init(mb + 8u * s, 1);
            mbar_init(mb + 24u + 8u * s, 128);
        }
        mbar_init(mb + 48u, 1);
    }
    __syncthreads();

    const char* Yb = (const char*)A;
    if (tid == 0) {
        mbar_expect(mb + 48u, 65536u);
        cpbulk(sb, (const char*)Bm + (size_t)panel * 65536, 65536u, mb + 48u);
#pragma unroll
        for (int I = 0; I < 2; I++) {       // fresh stages: no empty wait
            mbar_expect(mb + 8u * I, 16384u);
            cpbulk(sb + 65536u + 16384u * I,
                   Yb + (size_t)(t0 * 4 + I) * 16384, 16384u, mb + 8u * I);
        }
    }
    mbar_wait(mb + 48u, 0);

    const int warp = tid >> 5, lane = tid & 31;
    const int m_w = (warp >> 1) * 64, n_w = (warp & 1) * 64;
    const int r = lane >> 2, tig = lane & 3;
    const int aoff = 65536 + (m_w + r) * 32 + tig * 8;
    const int boff = (n_w + r) * 32 + tig * 8;

    int L = 0;
#pragma unroll 1
    for (int t = t0; t < t1; t++) {
        float acc[4][8][4] = {};
#pragma unroll 1
        for (int j = 0; j < 4; j++, L++) {
            if (tid == 0) {
                const int I = L + 2;
                if (I < total) {
                    const int s = I % 3;
                    if (I >= 3) mbar_wait(mb + 24u + 8u * s, ((I / 3) & 1) ^ 1);
                    mbar_expect(mb + 8u * s, 16384u);
                    cpbulk(sb + 65536u + 16384u * (uint32_t)s,
                           Yb + (size_t)(t0 * 4 + I) * 16384, 16384u, mb + 8u * s);
                }
            }
            const int s = L % 3;
            mbar_wait(mb + 8u * s, (uint32_t)((L / 3) & 1));

            const char* sa  = smem + aoff + s * 16384;
            const char* sbp = smem + boff + j * 16384;   // panel slabs j*4..j*4+3
#pragma unroll
            for (int kg = 0; kg < 4; kg++) {
                const char* sk = sa + kg * 4096;
                const char* bk = sbp + kg * 4096;
                uint2 bf[8];
#pragma unroll
                for (int ni = 0; ni < 8; ni++)
                    bf[ni] = *(const uint2*)(bk + ni * 256);
#pragma unroll
                for (int mi = 0; mi < 4; mi++) {
                    uint2 alo = *(const uint2*)(sk + mi * 512);
                    uint2 ahi = *(const uint2*)(sk + mi * 512 + 256);
#pragma unroll
                    for (int ni = 0; ni < 8; ni++)
                        mma_bf16(acc[mi][ni], alo.x, ahi.x, alo.y, ahi.y,
                                 bf[ni].x, bf[ni].y);
                }
            }
            mbar_arrive(mb + 24u + 8u * s);
        }

        // epilogue: H in GEMM2 block layout (registers + global only)
        char* Cb = (char*)C;
#pragma unroll
        for (int ni = 0; ni < 8; ni++) {
            const int n = n0 + n_w + ni * 8 + 2 * tig;
            const float bn0 = __ldg(bias + n), bn1 = __ldg(bias + n + 1);
            const int p = (n >> 1) & 7, pos = ((p & 3) << 1) | (p >> 2);
            const size_t base = (size_t)(t * 16 + (n >> 6)) * 16384
                              + (size_t)((n >> 4) & 3) * 4096 + pos * 4;
#pragma unroll
            for (int mi = 0; mi < 4; mi++) {
                const int rr = m_w + mi * 16 + r;
                __nv_bfloat162 v01, v23;
                v01.x = __float2bfloat16(gelu_exact(acc[mi][ni][0] + bn0));
                v01.y = __float2bfloat16(gelu_exact(acc[mi][ni][1] + bn1));
                v23.x = __float2bfloat16(gelu_exact(acc[mi][ni][2] + bn0));
                v23.y = __float2bfloat16(gelu_exact(acc[mi][ni][3] + bn1));
                *(__nv_bfloat162*)(Cb + base + (size_t)rr * 32)       = v01;
                *(__nv_bfloat162*)(Cb + base + (size_t)(rr + 8) * 32) = v23;
            }
        }
    }
}

// ---------------------------------------------------------------------------
// GEMM2: out = H @ W2^T + b2 + x (transposed residual). grid (2, 1024).
// KC=64, 3 stages x 32KB (16KB A block + 16KB B block), 2 bulks/iter.
// ---------------------------------------------------------------------------
__global__ void __launch_bounds__(128, 2) gemm2_bf16(
    const __nv_bfloat16* __restrict__ A, const __nv_bfloat16* __restrict__ Bm,
    const float* __restrict__ bias, const float* __restrict__ xres,
    float* __restrict__ C)
{
    extern __shared__ char smem[];          // 3 x 32KB stages
    __shared__ uint64_t mbar[6];            // full0..2, empty0..2
    const uint32_t sb = smem_u32(smem);
    const uint32_t mb = smem_u32(mbar);

    const int tid = threadIdx.x;
    const int t = blockIdx.y;               // m-tile
    const int panel = blockIdx.x;           // 0..1
    const int m0 = t * 128, n0 = panel * 128;
    const char* Hb = (const char*)A;
    const char* Wb = (const char*)Bm;

    if (tid == 0) {
#pragma unroll
        for (int s = 0; s < 3; s++) {
            mbar_init(mb + 8u * s, 1);
            mbar_init(mb + 24u + 8u * s, 128);
        }
    }
    __syncthreads();

#define ISSUE2(I) do {                                                        \
    const int s_ = (I) % 3;                                                   \
    if ((I) >= 3) mbar_wait(mb + 24u + 8u * s_, (((I) / 3) & 1) ^ 1);         \
    mbar_expect(mb + 8u * s_, 32768u);                                        \
    cpbulk(sb + 32768u * (uint32_t)s_,                                        \
           Hb + (size_t)(t * 16 + (I)) * 16384, 16384u, mb + 8u * s_);        \
    cpbulk(sb + 32768u * (uint32_t)s_ + 16384u,                               \
           Wb + (size_t)(panel * 16 + (I)) * 16384, 16384u, mb + 8u * s_);    \
} while (0)

    if (tid == 0) { ISSUE2(0); ISSUE2(1); }

    const int warp = tid >> 5, lane = tid & 31;
    const int m_w = (warp >> 1) * 64, n_w = (warp & 1) * 64;
    const int r = lane >> 2, tig = lane & 3;
    const int aoff = (m_w + r) * 32 + tig * 8;
    const int boff = 16384 + (n_w + r) * 32 + tig * 8;

    float acc[4][8][4] = {};

#pragma unroll 1
    for (int L = 0; L < 16; L++) {
        if (tid == 0 && L + 2 < 16) ISSUE2(L + 2);
        const int s = L % 3;
        mbar_wait(mb + 8u * s, (uint32_t)((L / 3) & 1));

        const char* st = smem + (size_t)s * 32768;
#pragma unroll
        for (int kg = 0; kg < 4; kg++) {
            const char* sk = st + aoff + kg * 4096;
            const char* bk = st + boff + kg * 4096;
            uint2 bf[8];
#pragma unroll
            for (int ni = 0; ni < 8; ni++)
                bf[ni] = *(const uint2*)(bk + ni * 256);
#pragma unroll
            for (int mi = 0; mi < 4; mi++) {
                uint2 alo = *(const uint2*)(sk + mi * 512);
                uint2 ahi = *(const uint2*)(sk + mi * 512 + 256);
#pragma unroll
                for (int ni = 0; ni < 8; ni++)
                    mma_bf16(acc[mi][ni], alo.x, ahi.x, alo.y, ahi.y,
                             bf[ni].x, bf[ni].y);
            }
        }
        mbar_arrive(mb + 24u + 8u * s);
    }
#undef ISSUE2

    __syncthreads();                        // all bulks done (all 16 waited)
    float* tile = (float*)smem;
#pragma unroll
    for (int ni = 0; ni < 8; ni++) {
        const int n_l = n_w + ni * 8 + 2 * tig;
#pragma unroll
        for (int mi = 0; mi < 4; mi++) {
            const int m_l = m_w + mi * 16 + r;
            tile[n_l * 132 + m_l]           = acc[mi][ni][0];
            tile[(n_l + 1) * 132 + m_l]     = acc[mi][ni][1];
            tile[n_l * 132 + m_l + 8]       = acc[mi][ni][2];
            tile[(n_l + 1) * 132 + m_l + 8] = acc[mi][ni][3];
        }
    }
    __syncthreads();
    const int bb = m0 >> 16, cc = (m0 >> 8) & 255, h0 = m0 & 255;
#pragma unroll
    for (int itr = 0; itr < 32; itr++) {
        const int nl = warp + itr * 4;
        const float bj = __ldg(bias + n0 + nl);
        size_t base = ((size_t)bb << 24) + ((size_t)(n0 + nl) << 16)
                    + ((size_t)cc << 8) + (size_t)h0 + (size_t)(lane * 4);
        float4 tv = *(float4*)&tile[nl * 132 + lane * 4];
        float4 xv = *(const float4*)&xres[base];
        *(float4*)&C[base] = make_float4(tv.x + bj + xv.x, tv.y + bj + xv.y,
                                         tv.z + bj + xv.z, tv.w + bj + xv.w);
    }
}

// ---------------------------------------------------------------------------
extern "C" void kernel_launch(void* const* d_in, const int* in_sizes, int n_in,
                              void* d_out, int out_size)
{
    (void)in_sizes; (void)n_in; (void)out_size;
    const float* x   = (const float*)d_in[0];
    const float* cw  = (const float*)d_in[1];
    const float* cb  = (const float*)d_in[2];
    const float* g   = (const float*)d_in[3];
    const float* bta = (const float*)d_in[4];
    const float* w1  = (const float*)d_in[5];
    const float* b1  = (const float*)d_in[6];
    const float* w2  = (const float*)d_in[7];
    const float* b2  = (const float*)d_in[8];
    float* out = (float*)d_out;

    __nv_bfloat16 *Y, *H, *W1, *W2;
    cudaGetSymbolAddress((void**)&Y,  g_Y);
    cudaGetSymbolAddress((void**)&H,  g_H);
    cudaGetSymbolAddress((void**)&W1, g_W1);
    cudaGetSymbolAddress((void**)&W2, g_W2);

    const int SMEM_G1 = 114688;  // 64KB panel + 3 x 16KB A stages
    const int SMEM_G2 = 98304;   // 3 x 32KB stages (>= 67.6KB transpose tile)
    cudaFuncSetAttribute(gemm1_persist,
                         cudaFuncAttributeMaxDynamicSharedMemorySize, SMEM_G1);
    cudaFuncSetAttribute(gemm2_bf16,
                         cudaFuncAttributeMaxDynamicSharedMemorySize, SMEM_G2);

    // 0) weights -> bf16 block layouts
    prep_w1<<<(HID * DIM + 255) / 256, 256>>>(w1, W1);
    prep_w2<<<(DIM * HID + 255) / 256, 256>>>(w2, W2);

    // 1) depthwise conv + bias + LayerNorm(W) -> Y (bf16 tile-blocks)
    conv_ln_kernel<<<dim3(DIM / 4, DIM, BATCH), 128>>>(x, cw, cb, g, bta, Y);

    // 2) GEMM1 persistent + GELU -> H (bf16 tile-blocks)
    gemm1_persist<<<296, 128, SMEM_G1>>>(Y, W1, b1, H);

    // 3) GEMM2 + bias + transposed residual -> out (fp32)
    gemm2_bf16<<<dim3(2, M_ROWS / 128), 128, SMEM_G2>>>(H, W2, b2, x, out);
}

// round 11
// speedup vs baseline: 1.9662x; 1.2182x over previous
#include <cuda_runtime.h>
#include <cuda_bf16.h>
#include <cstdint>

#define DIM 256
#define BATCH 2
#define M_ROWS (BATCH * DIM * DIM)   // 131072
#define HID (4 * DIM)                // 1024
#define EPS_LN 1e-5f

// Scratch. GEMM operands in TILE-BLOCK layout: 16KB block = (128 rows x 64 k)
// = 4 kg-slabs of 4KB; slab = row*32B; within 32B: 8 bf16-pairs at permuted
// position pos(p)=((p&3)<<1)|(p>>2), p=(k>>1)&7. Blocks are contiguous so a
// whole stage loads with ONE cp.async.bulk.
//   Y  blocks: (m-tile t)*4  + (k>>6)            [GEMM1 A, K=256]
//   H  blocks: (m-tile t)*16 + (k>>6)            [GEMM2 A, K=1024]
//   W1 panels: panel p = 64KB contiguous (slab = k>>4, 16 slabs)
//   W2 blocks: (panel p)*16 + (k>>6)
__device__ __align__(256) __nv_bfloat16 g_Y[(size_t)M_ROWS * DIM];
__device__ __align__(256) __nv_bfloat16 g_H[(size_t)M_ROWS * HID];
__device__ __align__(256) __nv_bfloat16 g_W1[(size_t)HID * DIM];
__device__ __align__(256) __nv_bfloat16 g_W2[(size_t)DIM * HID];

// ---------------------------------------------------------------------------
// helpers
// ---------------------------------------------------------------------------
__device__ __forceinline__ uint32_t smem_u32(const void* p) {
    uint32_t a;
    asm("{ .reg .u64 t; cvta.to.shared.u64 t, %1; cvt.u32.u64 %0, t; }"
        : "=r"(a) : "l"(p));
    return a;
}
__device__ __forceinline__ void mbar_init(uint32_t a, uint32_t cnt) {
    asm volatile("mbarrier.init.shared.b64 [%0], %1;" :: "r"(a), "r"(cnt) : "memory");
}
__device__ __forceinline__ void mbar_expect(uint32_t a, uint32_t tx) {
    asm volatile("mbarrier.arrive.expect_tx.shared.b64 _, [%0], %1;"
                 :: "r"(a), "r"(tx) : "memory");
}
__device__ __forceinline__ void mbar_arrive(uint32_t a) {
    asm volatile("mbarrier.arrive.shared.b64 _, [%0];" :: "r"(a) : "memory");
}
__device__ __forceinline__ void mbar_wait(uint32_t a, uint32_t parity) {
    asm volatile(
        "{\n\t.reg .pred P;\n\t"
        "W_%=:\n\t"
        "mbarrier.try_wait.parity.shared.b64 P, [%0], %1, 0x989680;\n\t"
        "@!P bra W_%=;\n\t}"
        :: "r"(a), "r"(parity) : "memory");
}
__device__ __forceinline__ void cpbulk(uint32_t dst, const void* src,
                                       uint32_t bytes, uint32_t mbar) {
    asm volatile(
        "cp.async.bulk.shared::cluster.global.mbarrier::complete_tx::bytes "
        "[%0], [%1], %2, [%3];"
        :: "r"(dst), "l"(src), "r"(bytes), "r"(mbar) : "memory");
}
__device__ __forceinline__ void mma_bf16(float* c, uint32_t a0, uint32_t a1,
                                         uint32_t a2, uint32_t a3,
                                         uint32_t b0, uint32_t b1) {
    asm volatile(
        "mma.sync.aligned.m16n8k16.row.col.f32.bf16.bf16.f32 "
        "{%0,%1,%2,%3}, {%4,%5,%6,%7}, {%8,%9}, {%0,%1,%2,%3};"
        : "+f"(c[0]), "+f"(c[1]), "+f"(c[2]), "+f"(c[3])
        : "r"(a0), "r"(a1), "r"(a2), "r"(a3), "r"(b0), "r"(b1));
}
// Fast GELU: tanh formulation with HW MUFU.TANH. Error << bf16 ulp of H.
__device__ __forceinline__ float gelu_fast(float v) {
    float inner = 0.7978845608028654f * v * fmaf(0.044715f, v * v, 1.0f);
    float t;
    asm("tanh.approx.f32 %0, %1;" : "=f"(t) : "f"(inner));
    float hv = 0.5f * v;
    return fmaf(hv, t, hv);
}

// ---------------------------------------------------------------------------
// weight prep
// ---------------------------------------------------------------------------
__global__ void prep_w1(const float* __restrict__ src, __nv_bfloat16* __restrict__ dst) {
    int i = blockIdx.x * blockDim.x + threadIdx.x;
    if (i < HID * DIM) {
        int n = i / DIM, k = i - n * DIM;
        int p = (k >> 1) & 7, pos = ((p & 3) << 1) | (p >> 2);
        size_t byte = (size_t)(n >> 7) * 65536 + (size_t)(k >> 4) * 4096
                    + (size_t)(n & 127) * 32 + pos * 4 + (k & 1) * 2;
        *(__nv_bfloat16*)((char*)dst + byte) = __float2bfloat16(src[i]);
    }
}
__global__ void prep_w2(const float* __restrict__ src, __nv_bfloat16* __restrict__ dst) {
    int i = blockIdx.x * blockDim.x + threadIdx.x;
    if (i < DIM * HID) {
        int n = i / HID, k = i - n * HID;
        int p = (k >> 1) & 7, pos = ((p & 3) << 1) | (p >> 2);
        size_t byte = (size_t)((n >> 7) * 16 + (k >> 6)) * 16384
                    + (size_t)((k >> 4) & 3) * 4096
                    + (size_t)(n & 127) * 32 + pos * 4 + (k & 1) * 2;
        *(__nv_bfloat16*)((char*)dst + byte) = __float2bfloat16(src[i]);
    }
}

// ---------------------------------------------------------------------------
// Kernel 1: depthwise 7x7 conv + bias + LayerNorm over W (unchanged from R10)
// ---------------------------------------------------------------------------
__global__ __launch_bounds__(128) void conv_ln_kernel(
    const float* __restrict__ x, const float* __restrict__ cw,
    const float* __restrict__ cb, const float* __restrict__ g,
    const float* __restrict__ bta, __nv_bfloat16* __restrict__ Y)
{
    __shared__ float s[10 * 262];
    __shared__ float swts[49];
    __shared__ float red[2][4][4];

    const int h0 = blockIdx.x * 4;
    const int c = blockIdx.y, b = blockIdx.z;
    const int tid = threadIdx.x;
    const int w0 = tid * 2;

    if (tid < 49) swts[tid] = cw[c * 49 + tid];

    const float* xp = x + ((size_t)(b * DIM + c)) * DIM * DIM;
    for (int i = tid; i < 10 * 262; i += 128) {
        int ro = i / 262, col = i - ro * 262;
        int hh = h0 - 3 + ro, ww = col - 3;
        float v = 0.f;
        if (hh >= 0 && hh < DIM && ww >= 0 && ww < DIM) v = xp[hh * DIM + ww];
        s[i] = v;
    }
    __syncthreads();

    float wr[49];
#pragma unroll
    for (int i = 0; i < 49; i++) wr[i] = swts[i];

    const float cbc = cb[c];
    float a0[4], a1[4];
#pragma unroll
    for (int r = 0; r < 4; r++) { a0[r] = cbc; a1[r] = cbc; }

#pragma unroll
    for (int ro = 0; ro < 10; ro++) {
        float2 p0 = *(const float2*)&s[ro * 262 + w0];
        float2 p1 = *(const float2*)&s[ro * 262 + w0 + 2];
        float2 p2 = *(const float2*)&s[ro * 262 + w0 + 4];
        float2 p3 = *(const float2*)&s[ro * 262 + w0 + 6];
        float v[8] = {p0.x, p0.y, p1.x, p1.y, p2.x, p2.y, p3.x, p3.y};
#pragma unroll
        for (int r = 0; r < 4; r++) {
            const int kh = ro - r;
            if (kh >= 0 && kh < 7) {
#pragma unroll
                for (int kw = 0; kw < 7; kw++) {
                    a0[r] += v[kw]     * wr[kh * 7 + kw];
                    a1[r] += v[kw + 1] * wr[kh * 7 + kw];
                }
            }
        }
    }

    const int lane = tid & 31, warp = tid >> 5;
#pragma unroll
    for (int r = 0; r < 4; r++) {
        float sv = a0[r] + a1[r];
        float sq = a0[r] * a0[r] + a1[r] * a1[r];
#pragma unroll
        for (int o = 16; o; o >>= 1) {
            sv += __shfl_xor_sync(0xffffffffu, sv, o);
            sq += __shfl_xor_sync(0xffffffffu, sq, o);
        }
        if (lane == 0) { red[0][r][warp] = sv; red[1][r][warp] = sq; }
    }
    __syncthreads();

    const float gv0 = g[w0], gv1 = g[w0 + 1];
    const float bv0 = bta[w0], bv1 = bta[w0 + 1];
    const int p = tid & 7, pos = ((p & 3) << 1) | (p >> 2);
    const int j = w0 >> 6, kgl = (w0 >> 4) & 3;
    const size_t mbase = (size_t)(b * DIM + c) * DIM;
#pragma unroll
    for (int r = 0; r < 4; r++) {
        float S  = red[0][r][0] + red[0][r][1] + red[0][r][2] + red[0][r][3];
        float S2 = red[1][r][0] + red[1][r][1] + red[1][r][2] + red[1][r][3];
        float mu  = S * (1.f / 256.f);
        float var = S2 * (1.f / 256.f) - mu * mu;
        float inv = rsqrtf(var + EPS_LN);
        __nv_bfloat162 o;
        o.x = __float2bfloat16((a0[r] - mu) * inv * gv0 + bv0);
        o.y = __float2bfloat16((a1[r] - mu) * inv * gv1 + bv1);
        const size_t m = mbase + h0 + r;
        const size_t byte = (size_t)((m >> 7) * 4 + j) * 16384
                          + kgl * 4096 + (m & 127) * 32 + pos * 4;
        *(__nv_bfloat162*)((char*)Y + byte) = o;
    }
}

// ---------------------------------------------------------------------------
// GEMM1 persistent: H = gelu(Y @ W1^T + b1). 296 CTAs (8 panels x 37 groups).
// Resident 64KB W1 panel + 3 x 16KB A stages (1 bulk each, KC=64).
// Epilogue: fast-tanh GELU + paired STG.64 into H's tile-block layout.
// ---------------------------------------------------------------------------
__global__ void __launch_bounds__(128, 2) gemm1_persist(
    const __nv_bfloat16* __restrict__ A, const __nv_bfloat16* __restrict__ Bm,
    const float* __restrict__ bias, __nv_bfloat16* __restrict__ C)
{
    constexpr int NGR = 37;
    extern __shared__ char smem[];          // [0,64K) panel, [64K,112K) stages
    __shared__ uint64_t mbar[7];            // full0..2, empty0..2, panel
    const uint32_t sb = smem_u32(smem);
    const uint32_t mb = smem_u32(mbar);

    const int tid = threadIdx.x;
    const int panel = blockIdx.x & 7;
    const int gr = blockIdx.x >> 3;
    const int t0 = (gr * 1024) / NGR, t1 = ((gr + 1) * 1024) / NGR;
    const int n0 = panel * 128;
    const int total = (t1 - t0) * 4;

    if (tid == 0) {
#pragma unroll
        for (int s = 0; s < 3; s++) {
            mbar_init(mb + 8u * s, 1);
            mbar_init(mb + 24u + 8u * s, 128);
        }
        mbar_init(mb + 48u, 1);
    }
    __syncthreads();

    const char* Yb = (const char*)A;
    if (tid == 0) {
        mbar_expect(mb + 48u, 65536u);
        cpbulk(sb, (const char*)Bm + (size_t)panel * 65536, 65536u, mb + 48u);
#pragma unroll
        for (int I = 0; I < 2; I++) {       // fresh stages: no empty wait
            mbar_expect(mb + 8u * I, 16384u);
            cpbulk(sb + 65536u + 16384u * I,
                   Yb + (size_t)(t0 * 4 + I) * 16384, 16384u, mb + 8u * I);
        }
    }
    mbar_wait(mb + 48u, 0);

    const int warp = tid >> 5, lane = tid & 31;
    const int m_w = (warp >> 1) * 64, n_w = (warp & 1) * 64;
    const int r = lane >> 2, tig = lane & 3;
    const int aoff = 65536 + (m_w + r) * 32 + tig * 8;
    const int boff = (n_w + r) * 32 + tig * 8;

    int L = 0;
#pragma unroll 1
    for (int t = t0; t < t1; t++) {
        float acc[4][8][4] = {};
#pragma unroll 1
        for (int j = 0; j < 4; j++, L++) {
            if (tid == 0) {
                const int I = L + 2;
                if (I < total) {
                    const int s = I % 3;
                    if (I >= 3) mbar_wait(mb + 24u + 8u * s, ((I / 3) & 1) ^ 1);
                    mbar_expect(mb + 8u * s, 16384u);
                    cpbulk(sb + 65536u + 16384u * (uint32_t)s,
                           Yb + (size_t)(t0 * 4 + I) * 16384, 16384u, mb + 8u * s);
                }
            }
            const int s = L % 3;
            mbar_wait(mb + 8u * s, (uint32_t)((L / 3) & 1));

            const char* sa  = smem + aoff + s * 16384;
            const char* sbp = smem + boff + j * 16384;   // panel slabs j*4..j*4+3
#pragma unroll
            for (int kg = 0; kg < 4; kg++) {
                const char* sk = sa + kg * 4096;
                const char* bk = sbp + kg * 4096;
                uint2 bf[8];
#pragma unroll
                for (int ni = 0; ni < 8; ni++)
                    bf[ni] = *(const uint2*)(bk + ni * 256);
#pragma unroll
                for (int mi = 0; mi < 4; mi++) {
                    uint2 alo = *(const uint2*)(sk + mi * 512);
                    uint2 ahi = *(const uint2*)(sk + mi * 512 + 256);
#pragma unroll
                    for (int ni = 0; ni < 8; ni++)
                        mma_bf16(acc[mi][ni], alo.x, ahi.x, alo.y, ahi.y,
                                 bf[ni].x, bf[ni].y);
                }
            }
            mbar_arrive(mb + 24u + 8u * s);
        }

        // epilogue: fast GELU, bf16x2 pair-converts, STG.64 paired stores.
        // pair (ni=2q, 2q+1): n and n+8 land at adjacent pos slots (2tig,
        // 2tig+1) in the same slab -> one uint2 store per row.
        char* Cb = (char*)C;
#pragma unroll
        for (int q = 0; q < 4; q++) {
            const int ne = n0 + n_w + q * 16 + 2 * tig;   // even-ni column
            const float be0 = __ldg(bias + ne),     be1 = __ldg(bias + ne + 1);
            const float bo0 = __ldg(bias + ne + 8), bo1 = __ldg(bias + ne + 9);
            const size_t base = (size_t)(t * 16 + (ne >> 6)) * 16384
                              + (size_t)((ne >> 4) & 3) * 4096 + tig * 8;
#pragma unroll
            for (int mi = 0; mi < 4; mi++) {
                const int rr = m_w + mi * 16 + r;
                const float* ae = acc[mi][2 * q];
                const float* ao = acc[mi][2 * q + 1];
                __nv_bfloat162 e0 = __floats2bfloat162_rn(
                    gelu_fast(ae[0] + be0), gelu_fast(ae[1] + be1));
                __nv_bfloat162 o0 = __floats2bfloat162_rn(
                    gelu_fast(ao[0] + bo0), gelu_fast(ao[1] + bo1));
                __nv_bfloat162 e1 = __floats2bfloat162_rn(
                    gelu_fast(ae[2] + be0), gelu_fast(ae[3] + be1));
                __nv_bfloat162 o1 = __floats2bfloat162_rn(
                    gelu_fast(ao[2] + bo0), gelu_fast(ao[3] + bo1));
                uint2 lo = make_uint2(*(uint32_t*)&e0, *(uint32_t*)&o0);
                uint2 hi = make_uint2(*(uint32_t*)&e1, *(uint32_t*)&o1);
                *(uint2*)(Cb + base + (size_t)rr * 32)       = lo;
                *(uint2*)(Cb + base + (size_t)(rr + 8) * 32) = hi;
            }
        }
    }
}

// ---------------------------------------------------------------------------
// GEMM2 (unchanged from R10): out = H @ W2^T + b2 + x (transposed residual).
// ---------------------------------------------------------------------------
__global__ void __launch_bounds__(128, 2) gemm2_bf16(
    const __nv_bfloat16* __restrict__ A, const __nv_bfloat16* __restrict__ Bm,
    const float* __restrict__ bias, const float* __restrict__ xres,
    float* __restrict__ C)
{
    extern __shared__ char smem[];          // 3 x 32KB stages
    __shared__ uint64_t mbar[6];            // full0..2, empty0..2
    const uint32_t sb = smem_u32(smem);
    const uint32_t mb = smem_u32(mbar);

    const int tid = threadIdx.x;
    const int t = blockIdx.y;               // m-tile
    const int panel = blockIdx.x;           // 0..1
    const int m0 = t * 128, n0 = panel * 128;
    const char* Hb = (const char*)A;
    const char* Wb = (const char*)Bm;

    if (tid == 0) {
#pragma unroll
        for (int s = 0; s < 3; s++) {
            mbar_init(mb + 8u * s, 1);
            mbar_init(mb + 24u + 8u * s, 128);
        }
    }
    __syncthreads();

#define ISSUE2(I) do {                                                        \
    const int s_ = (I) % 3;                                                   \
    if ((I) >= 3) mbar_wait(mb + 24u + 8u * s_, (((I) / 3) & 1) ^ 1);         \
    mbar_expect(mb + 8u * s_, 32768u);                                        \
    cpbulk(sb + 32768u * (uint32_t)s_,                                        \
           Hb + (size_t)(t * 16 + (I)) * 16384, 16384u, mb + 8u * s_);        \
    cpbulk(sb + 32768u * (uint32_t)s_ + 16384u,                               \
           Wb + (size_t)(panel * 16 + (I)) * 16384, 16384u, mb + 8u * s_);    \
} while (0)

    if (tid == 0) { ISSUE2(0); ISSUE2(1); }

    const int warp = tid >> 5, lane = tid & 31;
    const int m_w = (warp >> 1) * 64, n_w = (warp & 1) * 64;
    const int r = lane >> 2, tig = lane & 3;
    const int aoff = (m_w + r) * 32 + tig * 8;
    const int boff = 16384 + (n_w + r) * 32 + tig * 8;

    float acc[4][8][4] = {};

#pragma unroll 1
    for (int L = 0; L < 16; L++) {
        if (tid == 0 && L + 2 < 16) ISSUE2(L + 2);
        const int s = L % 3;
        mbar_wait(mb + 8u * s, (uint32_t)((L / 3) & 1));

        const char* st = smem + (size_t)s * 32768;
#pragma unroll
        for (int kg = 0; kg < 4; kg++) {
            const char* sk = st + aoff + kg * 4096;
            const char* bk = st + boff + kg * 4096;
            uint2 bf[8];
#pragma unroll
            for (int ni = 0; ni < 8; ni++)
                bf[ni] = *(const uint2*)(bk + ni * 256);
#pragma unroll
            for (int mi = 0; mi < 4; mi++) {
                uint2 alo = *(const uint2*)(sk + mi * 512);
                uint2 ahi = *(const uint2*)(sk + mi * 512 + 256);
#pragma unroll
                for (int ni = 0; ni < 8; ni++)
                    mma_bf16(acc[mi][ni], alo.x, ahi.x, alo.y, ahi.y,
                             bf[ni].x, bf[ni].y);
            }
        }
        mbar_arrive(mb + 24u + 8u * s);
    }
#undef ISSUE2

    __syncthreads();                        // all bulks done (all 16 waited)
    float* tile = (float*)smem;
#pragma unroll
    for (int ni = 0; ni < 8; ni++) {
        const int n_l = n_w + ni * 8 + 2 * tig;
#pragma unroll
        for (int mi = 0; mi < 4; mi++) {
            const int m_l = m_w + mi * 16 + r;
            tile[n_l * 132 + m_l]           = acc[mi][ni][0];
            tile[(n_l + 1) * 132 + m_l]     = acc[mi][ni][1];
            tile[n_l * 132 + m_l + 8]       = acc[mi][ni][2];
            tile[(n_l + 1) * 132 + m_l + 8] = acc[mi][ni][3];
        }
    }
    __syncthreads();
    const int bb = m0 >> 16, cc = (m0 >> 8) & 255, h0 = m0 & 255;
#pragma unroll
    for (int itr = 0; itr < 32; itr++) {
        const int nl = warp + itr * 4;
        const float bj = __ldg(bias + n0 + nl);
        size_t base = ((size_t)bb << 24) + ((size_t)(n0 + nl) << 16)
                    + ((size_t)cc << 8) + (size_t)h0 + (size_t)(lane * 4);
        float4 tv = *(float4*)&tile[nl * 132 + lane * 4];
        float4 xv = *(const float4*)&xres[base];
        *(float4*)&C[base] = make_float4(tv.x + bj + xv.x, tv.y + bj + xv.y,
                                         tv.z + bj + xv.z, tv.w + bj + xv.w);
    }
}

// ---------------------------------------------------------------------------
extern "C" void kernel_launch(void* const* d_in, const int* in_sizes, int n_in,
                              void* d_out, int out_size)
{
    (void)in_sizes; (void)n_in; (void)out_size;
    const float* x   = (const float*)d_in[0];
    const float* cw  = (const float*)d_in[1];
    const float* cb  = (const float*)d_in[2];
    const float* g   = (const float*)d_in[3];
    const float* bta = (const float*)d_in[4];
    const float* w1  = (const float*)d_in[5];
    const float* b1  = (const float*)d_in[6];
    const float* w2  = (const float*)d_in[7];
    const float* b2  = (const float*)d_in[8];
    float* out = (float*)d_out;

    __nv_bfloat16 *Y, *H, *W1, *W2;
    cudaGetSymbolAddress((void**)&Y,  g_Y);
    cudaGetSymbolAddress((void**)&H,  g_H);
    cudaGetSymbolAddress((void**)&W1, g_W1);
    cudaGetSymbolAddress((void**)&W2, g_W2);

    const int SMEM_G1 = 114688;  // 64KB panel + 3 x 16KB A stages
    const int SMEM_G2 = 98304;   // 3 x 32KB stages (>= 67.6KB transpose tile)
    cudaFuncSetAttribute(gemm1_persist,
                         cudaFuncAttributeMaxDynamicSharedMemorySize, SMEM_G1);
    cudaFuncSetAttribute(gemm2_bf16,
                         cudaFuncAttributeMaxDynamicSharedMemorySize, SMEM_G2);

    // 0) weights -> bf16 block layouts
    prep_w1<<<(HID * DIM + 255) / 256, 256>>>(w1, W1);
    prep_w2<<<(DIM * HID + 255) / 256, 256>>>(w2, W2);

    // 1) depthwise conv + bias + LayerNorm(W) -> Y (bf16 tile-blocks)
    conv_ln_kernel<<<dim3(DIM / 4, DIM, BATCH), 128>>>(x, cw, cb, g, bta, Y);

    // 2) GEMM1 persistent + fast GELU -> H (bf16 tile-blocks)
    gemm1_persist<<<296, 128, SMEM_G1>>>(Y, W1, b1, H);

    // 3) GEMM2 + bias + transposed residual -> out (fp32)
    gemm2_bf16<<<dim3(2, M_ROWS / 128), 128, SMEM_G2>>>(H, W2, b2, x, out);
}

// round 12
// speedup vs baseline: 1.9851x; 1.0096x over previous
#include <cuda_runtime.h>
#include <cuda_bf16.h>
#include <cstdint>

#define DIM 256
#define BATCH 2
#define M_ROWS (BATCH * DIM * DIM)   // 131072
#define HID (4 * DIM)                // 1024
#define EPS_LN 1e-5f

// Scratch. GEMM operands in TILE-BLOCK layout: 16KB block = (128 rows x 64 k)
// = 4 kg-slabs of 4KB; slab = row*32B; within 32B: 8 bf16-pairs at permuted
// position pos(p)=((p&3)<<1)|(p>>2), p=(k>>1)&7. Blocks are contiguous so a
// whole stage loads with ONE cp.async.bulk.
__device__ __align__(256) __nv_bfloat16 g_Y[(size_t)M_ROWS * DIM];
__device__ __align__(256) __nv_bfloat16 g_H[(size_t)M_ROWS * HID];
__device__ __align__(256) __nv_bfloat16 g_W1[(size_t)HID * DIM];
__device__ __align__(256) __nv_bfloat16 g_W2[(size_t)DIM * HID];

// ---------------------------------------------------------------------------
// helpers
// ---------------------------------------------------------------------------
__device__ __forceinline__ uint32_t smem_u32(const void* p) {
    uint32_t a;
    asm("{ .reg .u64 t; cvta.to.shared.u64 t, %1; cvt.u32.u64 %0, t; }"
        : "=r"(a) : "l"(p));
    return a;
}
__device__ __forceinline__ void mbar_init(uint32_t a, uint32_t cnt) {
    asm volatile("mbarrier.init.shared.b64 [%0], %1;" :: "r"(a), "r"(cnt) : "memory");
}
__device__ __forceinline__ void mbar_expect(uint32_t a, uint32_t tx) {
    asm volatile("mbarrier.arrive.expect_tx.shared.b64 _, [%0], %1;"
                 :: "r"(a), "r"(tx) : "memory");
}
__device__ __forceinline__ void mbar_arrive(uint32_t a) {
    asm volatile("mbarrier.arrive.shared.b64 _, [%0];" :: "r"(a) : "memory");
}
__device__ __forceinline__ void mbar_wait(uint32_t a, uint32_t parity) {
    asm volatile(
        "{\n\t.reg .pred P;\n\t"
        "W_%=:\n\t"
        "mbarrier.try_wait.parity.shared.b64 P, [%0], %1, 0x989680;\n\t"
        "@!P bra W_%=;\n\t}"
        :: "r"(a), "r"(parity) : "memory");
}
__device__ __forceinline__ void cpbulk(uint32_t dst, const void* src,
                                       uint32_t bytes, uint32_t mbar) {
    asm volatile(
        "cp.async.bulk.shared::cluster.global.mbarrier::complete_tx::bytes "
        "[%0], [%1], %2, [%3];"
        :: "r"(dst), "l"(src), "r"(bytes), "r"(mbar) : "memory");
}
__device__ __forceinline__ void mma_bf16(float* c, uint32_t a0, uint32_t a1,
                                         uint32_t a2, uint32_t a3,
                                         uint32_t b0, uint32_t b1) {
    asm volatile(
        "mma.sync.aligned.m16n8k16.row.col.f32.bf16.bf16.f32 "
        "{%0,%1,%2,%3}, {%4,%5,%6,%7}, {%8,%9}, {%0,%1,%2,%3};"
        : "+f"(c[0]), "+f"(c[1]), "+f"(c[2]), "+f"(c[3])
        : "r"(a0), "r"(a1), "r"(a2), "r"(a3), "r"(b0), "r"(b1));
}
// Fast GELU: tanh formulation with HW MUFU.TANH. Error << bf16 ulp of H.
__device__ __forceinline__ float gelu_fast(float v) {
    float inner = 0.7978845608028654f * v * fmaf(0.044715f, v * v, 1.0f);
    float t;
    asm("tanh.approx.f32 %0, %1;" : "=f"(t) : "f"(inner));
    float hv = 0.5f * v;
    return fmaf(hv, t, hv);
}
// packed fp32 pair ops (FFMA2 path: PTX-only, ptxas never auto-fuses)
__device__ __forceinline__ uint64_t pack2(float lo, float hi) {
    uint64_t d;
    asm("mov.b64 %0, {%1, %2};" : "=l"(d) : "f"(lo), "f"(hi));
    return d;
}
__device__ __forceinline__ void unpack2(uint64_t v, float& lo, float& hi) {
    asm("mov.b64 {%0, %1}, %2;" : "=f"(lo), "=f"(hi) : "l"(v));
}
__device__ __forceinline__ void fma2(uint64_t& d, uint64_t a, uint64_t b) {
    asm("fma.rn.f32x2 %0, %1, %2, %0;" : "+l"(d) : "l"(a), "l"(b));
}
__device__ __forceinline__ uint64_t add2(uint64_t a, uint64_t b) {
    uint64_t d;
    asm("add.rn.f32x2 %0, %1, %2;" : "=l"(d) : "l"(a), "l"(b));
    return d;
}

// ---------------------------------------------------------------------------
// weight prep
// ---------------------------------------------------------------------------
__global__ void prep_w1(const float* __restrict__ src, __nv_bfloat16* __restrict__ dst) {
    int i = blockIdx.x * blockDim.x + threadIdx.x;
    if (i < HID * DIM) {
        int n = i / DIM, k = i - n * DIM;
        int p = (k >> 1) & 7, pos = ((p & 3) << 1) | (p >> 2);
        size_t byte = (size_t)(n >> 7) * 65536 + (size_t)(k >> 4) * 4096
                    + (size_t)(n & 127) * 32 + pos * 4 + (k & 1) * 2;
        *(__nv_bfloat16*)((char*)dst + byte) = __float2bfloat16(src[i]);
    }
}
__global__ void prep_w2(const float* __restrict__ src, __nv_bfloat16* __restrict__ dst) {
    int i = blockIdx.x * blockDim.x + threadIdx.x;
    if (i < DIM * HID) {
        int n = i / HID, k = i - n * HID;
        int p = (k >> 1) & 7, pos = ((p & 3) << 1) | (p >> 2);
        size_t byte = (size_t)((n >> 7) * 16 + (k >> 6)) * 16384
                    + (size_t)((k >> 4) & 3) * 4096
                    + (size_t)(n & 127) * 32 + pos * 4 + (k & 1) * 2;
        *(__nv_bfloat16*)((char*)dst + byte) = __float2bfloat16(src[i]);
    }
}

// ---------------------------------------------------------------------------
// Kernel 1: depthwise 7x7 conv + bias + LayerNorm over W.
// Math now in packed f32x2 (one FMA per (w, w+1) accumulator pair).
// ---------------------------------------------------------------------------
__global__ __launch_bounds__(128) void conv_ln_kernel(
    const float* __restrict__ x, const float* __restrict__ cw,
    const float* __restrict__ cb, const float* __restrict__ g,
    const float* __restrict__ bta, __nv_bfloat16* __restrict__ Y)
{
    __shared__ float s[10 * 262];
    __shared__ float swts[49];
    __shared__ float red[2][4][4];

    const int h0 = blockIdx.x * 4;
    const int c = blockIdx.y, b = blockIdx.z;
    const int tid = threadIdx.x;
    const int w0 = tid * 2;

    if (tid < 49) swts[tid] = cw[c * 49 + tid];

    const float* xp = x + ((size_t)(b * DIM + c)) * DIM * DIM;
    for (int i = tid; i < 10 * 262; i += 128) {
        int ro = i / 262, col = i - ro * 262;
        int hh = h0 - 3 + ro, ww = col - 3;
        float v = 0.f;
        if (hh >= 0 && hh < DIM && ww >= 0 && ww < DIM) v = xp[hh * DIM + ww];
        s[i] = v;
    }
    __syncthreads();

    uint64_t wp[49];
#pragma unroll
    for (int i = 0; i < 49; i++) { float w = swts[i]; wp[i] = pack2(w, w); }

    const float cbc = cb[c];
    uint64_t acc[4];
#pragma unroll
    for (int r = 0; r < 4; r++) acc[r] = pack2(cbc, cbc);

#pragma unroll
    for (int ro = 0; ro < 10; ro++) {
        float2 p0 = *(const float2*)&s[ro * 262 + w0];
        float2 p1 = *(const float2*)&s[ro * 262 + w0 + 2];
        float2 p2 = *(const float2*)&s[ro * 262 + w0 + 4];
        float2 p3 = *(const float2*)&s[ro * 262 + w0 + 6];
        float v[8] = {p0.x, p0.y, p1.x, p1.y, p2.x, p2.y, p3.x, p3.y};
        uint64_t vp[7];
#pragma unroll
        for (int kw = 0; kw < 7; kw++) vp[kw] = pack2(v[kw], v[kw + 1]);
#pragma unroll
        for (int r = 0; r < 4; r++) {
            const int kh = ro - r;
            if (kh >= 0 && kh < 7) {
#pragma unroll
                for (int kw = 0; kw < 7; kw++)
                    fma2(acc[r], vp[kw], wp[kh * 7 + kw]);
            }
        }
    }

    float a0[4], a1[4];
#pragma unroll
    for (int r = 0; r < 4; r++) unpack2(acc[r], a0[r], a1[r]);

    const int lane = tid & 31, warp = tid >> 5;
#pragma unroll
    for (int r = 0; r < 4; r++) {
        float sv = a0[r] + a1[r];
        float sq = a0[r] * a0[r] + a1[r] * a1[r];
#pragma unroll
        for (int o = 16; o; o >>= 1) {
            sv += __shfl_xor_sync(0xffffffffu, sv, o);
            sq += __shfl_xor_sync(0xffffffffu, sq, o);
        }
        if (lane == 0) { red[0][r][warp] = sv; red[1][r][warp] = sq; }
    }
    __syncthreads();

    const float gv0 = g[w0], gv1 = g[w0 + 1];
    const float bv0 = bta[w0], bv1 = bta[w0 + 1];
    const int p = tid & 7, pos = ((p & 3) << 1) | (p >> 2);
    const int j = w0 >> 6, kgl = (w0 >> 4) & 3;
    const size_t mbase = (size_t)(b * DIM + c) * DIM;
#pragma unroll
    for (int r = 0; r < 4; r++) {
        float S  = red[0][r][0] + red[0][r][1] + red[0][r][2] + red[0][r][3];
        float S2 = red[1][r][0] + red[1][r][1] + red[1][r][2] + red[1][r][3];
        float mu  = S * (1.f / 256.f);
        float var = S2 * (1.f / 256.f) - mu * mu;
        float inv = rsqrtf(var + EPS_LN);
        __nv_bfloat162 o;
        o.x = __float2bfloat16((a0[r] - mu) * inv * gv0 + bv0);
        o.y = __float2bfloat16((a1[r] - mu) * inv * gv1 + bv1);
        const size_t m = mbase + h0 + r;
        const size_t byte = (size_t)((m >> 7) * 4 + j) * 16384
                          + kgl * 4096 + (m & 127) * 32 + pos * 4;
        *(__nv_bfloat162*)((char*)Y + byte) = o;
    }
}

// ---------------------------------------------------------------------------
// GEMM1 persistent (unchanged from R11): H = gelu(Y @ W1^T + b1).
// ---------------------------------------------------------------------------
__global__ void __launch_bounds__(128, 2) gemm1_persist(
    const __nv_bfloat16* __restrict__ A, const __nv_bfloat16* __restrict__ Bm,
    const float* __restrict__ bias, __nv_bfloat16* __restrict__ C)
{
    constexpr int NGR = 37;
    extern __shared__ char smem[];          // [0,64K) panel, [64K,112K) stages
    __shared__ uint64_t mbar[7];            // full0..2, empty0..2, panel
    const uint32_t sb = smem_u32(smem);
    const uint32_t mb = smem_u32(mbar);

    const int tid = threadIdx.x;
    const int panel = blockIdx.x & 7;
    const int gr = blockIdx.x >> 3;
    const int t0 = (gr * 1024) / NGR, t1 = ((gr + 1) * 1024) / NGR;
    const int n0 = panel * 128;
    const int total = (t1 - t0) * 4;

    if (tid == 0) {
#pragma unroll
        for (int s = 0; s < 3; s++) {
            mbar_init(mb + 8u * s, 1);
            mbar_init(mb + 24u + 8u * s, 128);
        }
        mbar_init(mb + 48u, 1);
    }
    __syncthreads();

    const char* Yb = (const char*)A;
    if (tid == 0) {
        mbar_expect(mb + 48u, 65536u);
        cpbulk(sb, (const char*)Bm + (size_t)panel * 65536, 65536u, mb + 48u);
#pragma unroll
        for (int I = 0; I < 2; I++) {       // fresh stages: no empty wait
            mbar_expect(mb + 8u * I, 16384u);
            cpbulk(sb + 65536u + 16384u * I,
                   Yb + (size_t)(t0 * 4 + I) * 16384, 16384u, mb + 8u * I);
        }
    }
    mbar_wait(mb + 48u, 0);

    const int warp = tid >> 5, lane = tid & 31;
    const int m_w = (warp >> 1) * 64, n_w = (warp & 1) * 64;
    const int r = lane >> 2, tig = lane & 3;
    const int aoff = 65536 + (m_w + r) * 32 + tig * 8;
    const int boff = (n_w + r) * 32 + tig * 8;

    int L = 0;
#pragma unroll 1
    for (int t = t0; t < t1; t++) {
        float acc[4][8][4] = {};
#pragma unroll 1
        for (int j = 0; j < 4; j++, L++) {
            if (tid == 0) {
                const int I = L + 2;
                if (I < total) {
                    const int s = I % 3;
                    if (I >= 3) mbar_wait(mb + 24u + 8u * s, ((I / 3) & 1) ^ 1);
                    mbar_expect(mb + 8u * s, 16384u);
                    cpbulk(sb + 65536u + 16384u * (uint32_t)s,
                           Yb + (size_t)(t0 * 4 + I) * 16384, 16384u, mb + 8u * s);
                }
            }
            const int s = L % 3;
            mbar_wait(mb + 8u * s, (uint32_t)((L / 3) & 1));

            const char* sa  = smem + aoff + s * 16384;
            const char* sbp = smem + boff + j * 16384;   // panel slabs j*4..j*4+3
#pragma unroll
            for (int kg = 0; kg < 4; kg++) {
                const char* sk = sa + kg * 4096;
                const char* bk = sbp + kg * 4096;
                uint2 bf[8];
#pragma unroll
                for (int ni = 0; ni < 8; ni++)
                    bf[ni] = *(const uint2*)(bk + ni * 256);
#pragma unroll
                for (int mi = 0; mi < 4; mi++) {
                    uint2 alo = *(const uint2*)(sk + mi * 512);
                    uint2 ahi = *(const uint2*)(sk + mi * 512 + 256);
#pragma unroll
                    for (int ni = 0; ni < 8; ni++)
                        mma_bf16(acc[mi][ni], alo.x, ahi.x, alo.y, ahi.y,
                                 bf[ni].x, bf[ni].y);
                }
            }
            mbar_arrive(mb + 24u + 8u * s);
        }

        // epilogue: fast GELU, bf16x2 pair-converts, STG.64 paired stores.
        char* Cb = (char*)C;
#pragma unroll
        for (int q = 0; q < 4; q++) {
            const int ne = n0 + n_w + q * 16 + 2 * tig;   // even-ni column
            const float be0 = __ldg(bias + ne),     be1 = __ldg(bias + ne + 1);
            const float bo0 = __ldg(bias + ne + 8), bo1 = __ldg(bias + ne + 9);
            const size_t base = (size_t)(t * 16 + (ne >> 6)) * 16384
                              + (size_t)((ne >> 4) & 3) * 4096 + tig * 8;
#pragma unroll
            for (int mi = 0; mi < 4; mi++) {
                const int rr = m_w + mi * 16 + r;
                const float* ae = acc[mi][2 * q];
                const float* ao = acc[mi][2 * q + 1];
                __nv_bfloat162 e0 = __floats2bfloat162_rn(
                    gelu_fast(ae[0] + be0), gelu_fast(ae[1] + be1));
                __nv_bfloat162 o0 = __floats2bfloat162_rn(
                    gelu_fast(ao[0] + bo0), gelu_fast(ao[1] + bo1));
                __nv_bfloat162 e1 = __floats2bfloat162_rn(
                    gelu_fast(ae[2] + be0), gelu_fast(ae[3] + be1));
                __nv_bfloat162 o1 = __floats2bfloat162_rn(
                    gelu_fast(ao[2] + bo0), gelu_fast(ao[3] + bo1));
                uint2 lo = make_uint2(*(uint32_t*)&e0, *(uint32_t*)&o0);
                uint2 hi = make_uint2(*(uint32_t*)&e1, *(uint32_t*)&o1);
                *(uint2*)(Cb + base + (size_t)rr * 32)       = lo;
                *(uint2*)(Cb + base + (size_t)(rr + 8) * 32) = hi;
            }
        }
    }
}

// ---------------------------------------------------------------------------
// GEMM2: out = H @ W2^T + b2 + x. Residual adds now packed f32x2.
// ---------------------------------------------------------------------------
__global__ void __launch_bounds__(128, 2) gemm2_bf16(
    const __nv_bfloat16* __restrict__ A, const __nv_bfloat16* __restrict__ Bm,
    const float* __restrict__ bias, const float* __restrict__ xres,
    float* __restrict__ C)
{
    extern __shared__ char smem[];          // 3 x 32KB stages
    __shared__ uint64_t mbar[6];            // full0..2, empty0..2
    const uint32_t sb = smem_u32(smem);
    const uint32_t mb = smem_u32(mbar);

    const int tid = threadIdx.x;
    const int t = blockIdx.y;               // m-tile
    const int panel = blockIdx.x;           // 0..1
    const int m0 = t * 128, n0 = panel * 128;
    const char* Hb = (const char*)A;
    const char* Wb = (const char*)Bm;

    if (tid == 0) {
#pragma unroll
        for (int s = 0; s < 3; s++) {
            mbar_init(mb + 8u * s, 1);
            mbar_init(mb + 24u + 8u * s, 128);
        }
    }
    __syncthreads();

#define ISSUE2(I) do {                                                        \
    const int s_ = (I) % 3;                                                   \
    if ((I) >= 3) mbar_wait(mb + 24u + 8u * s_, (((I) / 3) & 1) ^ 1);         \
    mbar_expect(mb + 8u * s_, 32768u);                                        \
    cpbulk(sb + 32768u * (uint32_t)s_,                                        \
           Hb + (size_t)(t * 16 + (I)) * 16384, 16384u, mb + 8u * s_);        \
    cpbulk(sb + 32768u * (uint32_t)s_ + 16384u,                               \
           Wb + (size_t)(panel * 16 + (I)) * 16384, 16384u, mb + 8u * s_);    \
} while (0)

    if (tid == 0) { ISSUE2(0); ISSUE2(1); }

    const int warp = tid >> 5, lane = tid & 31;
    const int m_w = (warp >> 1) * 64, n_w = (warp & 1) * 64;
    const int r = lane >> 2, tig = lane & 3;
    const int aoff = (m_w + r) * 32 + tig * 8;
    const int boff = 16384 + (n_w + r) * 32 + tig * 8;

    float acc[4][8][4] = {};

#pragma unroll 1
    for (int L = 0; L < 16; L++) {
        if (tid == 0 && L + 2 < 16) ISSUE2(L + 2);
        const int s = L % 3;
        mbar_wait(mb + 8u * s, (uint32_t)((L / 3) & 1));

        const char* st = smem + (size_t)s * 32768;
#pragma unroll
        for (int kg = 0; kg < 4; kg++) {
            const char* sk = st + aoff + kg * 4096;
            const char* bk = st + boff + kg * 4096;
            uint2 bf[8];
#pragma unroll
            for (int ni = 0; ni < 8; ni++)
                bf[ni] = *(const uint2*)(bk + ni * 256);
#pragma unroll
            for (int mi = 0; mi < 4; mi++) {
                uint2 alo = *(const uint2*)(sk + mi * 512);
                uint2 ahi = *(const uint2*)(sk + mi * 512 + 256);
#pragma unroll
                for (int ni = 0; ni < 8; ni++)
                    mma_bf16(acc[mi][ni], alo.x, ahi.x, alo.y, ahi.y,
                             bf[ni].x, bf[ni].y);
            }
        }
        mbar_arrive(mb + 24u + 8u * s);
    }
#undef ISSUE2

    __syncthreads();                        // all bulks done (all 16 waited)
    float* tile = (float*)smem;
#pragma unroll
    for (int ni = 0; ni < 8; ni++) {
        const int n_l = n_w + ni * 8 + 2 * tig;
#pragma unroll
        for (int mi = 0; mi < 4; mi++) {
            const int m_l = m_w + mi * 16 + r;
            tile[n_l * 132 + m_l]           = acc[mi][ni][0];
            tile[(n_l + 1) * 132 + m_l]     = acc[mi][ni][1];
            tile[n_l * 132 + m_l + 8]       = acc[mi][ni][2];
            tile[(n_l + 1) * 132 + m_l + 8] = acc[mi][ni][3];
        }
    }
    __syncthreads();
    const int bb = m0 >> 16, cc = (m0 >> 8) & 255, h0 = m0 & 255;
#pragma unroll
    for (int itr = 0; itr < 32; itr++) {
        const int nl = warp + itr * 4;
        const float bj = __ldg(bias + n0 + nl);
        const uint64_t bjp = pack2(bj, bj);
        size_t base = ((size_t)bb << 24) + ((size_t)(n0 + nl) << 16)
                    + ((size_t)cc << 8) + (size_t)h0 + (size_t)(lane * 4);
        float4 tv = *(float4*)&tile[nl * 132 + lane * 4];
        float4 xv = *(const float4*)&xres[base];
        uint64_t* tp = (uint64_t*)&tv;
        const uint64_t* xp = (const uint64_t*)&xv;
        tp[0] = add2(add2(tp[0], bjp), xp[0]);
        tp[1] = add2(add2(tp[1], bjp), xp[1]);
        *(float4*)&C[base] = tv;
    }
}

// ---------------------------------------------------------------------------
extern "C" void kernel_launch(void* const* d_in, const int* in_sizes, int n_in,
                              void* d_out, int out_size)
{
    (void)in_sizes; (void)n_in; (void)out_size;
    const float* x   = (const float*)d_in[0];
    const float* cw  = (const float*)d_in[1];
    const float* cb  = (const float*)d_in[2];
    const float* g   = (const float*)d_in[3];
    const float* bta = (const float*)d_in[4];
    const float* w1  = (const float*)d_in[5];
    const float* b1  = (const float*)d_in[6];
    const float* w2  = (const float*)d_in[7];
    const float* b2  = (const float*)d_in[8];
    float* out = (float*)d_out;

    __nv_bfloat16 *Y, *H, *W1, *W2;
    cudaGetSymbolAddress((void**)&Y,  g_Y);
    cudaGetSymbolAddress((void**)&H,  g_H);
    cudaGetSymbolAddress((void**)&W1, g_W1);
    cudaGetSymbolAddress((void**)&W2, g_W2);

    const int SMEM_G1 = 114688;  // 64KB panel + 3 x 16KB A stages
    const int SMEM_G2 = 98304;   // 3 x 32KB stages (>= 67.6KB transpose tile)
    cudaFuncSetAttribute(gemm1_persist,
                         cudaFuncAttributeMaxDynamicSharedMemorySize, SMEM_G1);
    cudaFuncSetAttribute(gemm2_bf16,
                         cudaFuncAttributeMaxDynamicSharedMemorySize, SMEM_G2);

    // 0) weights -> bf16 block layouts
    prep_w1<<<(HID * DIM + 255) / 256, 256>>>(w1, W1);
    prep_w2<<<(DIM * HID + 255) / 256, 256>>>(w2, W2);

    // 1) depthwise conv + bias + LayerNorm(W) -> Y (bf16 tile-blocks)
    conv_ln_kernel<<<dim3(DIM / 4, DIM, BATCH), 128>>>(x, cw, cb, g, bta, Y);

    // 2) GEMM1 persistent + fast GELU -> H (bf16 tile-blocks)
    gemm1_persist<<<296, 128, SMEM_G1>>>(Y, W1, b1, H);

    // 3) GEMM2 + bias + transposed residual -> out (fp32)
    gemm2_bf16<<<dim3(2, M_ROWS / 128), 128, SMEM_G2>>>(H, W2, b2, x, out);
}

// round 13
// speedup vs baseline: 2.1135x; 1.0647x over previous
#include <cuda_runtime.h>
#include <cuda_bf16.h>
#include <cstdint>

#define DIM 256
#define BATCH 2
#define M_ROWS (BATCH * DIM * DIM)   // 131072
#define HID (4 * DIM)                // 1024
#define EPS_LN 1e-5f

// Scratch. GEMM operands in TILE-BLOCK layout: 16KB block = (128 rows x 64 k)
// = 4 kg-slabs of 4KB; slab = row*32B; within 32B: 8 bf16-pairs at permuted
// position pos(p)=((p&3)<<1)|(p>>2), p=(k>>1)&7. Blocks are contiguous so a
// whole stage loads with ONE cp.async.bulk.
__device__ __align__(256) __nv_bfloat16 g_Y[(size_t)M_ROWS * DIM];
__device__ __align__(256) __nv_bfloat16 g_H[(size_t)M_ROWS * HID];
__device__ __align__(256) __nv_bfloat16 g_W1[(size_t)HID * DIM];
__device__ __align__(256) __nv_bfloat16 g_W2[(size_t)DIM * HID];

// ---------------------------------------------------------------------------
// helpers
// ---------------------------------------------------------------------------
__device__ __forceinline__ uint32_t smem_u32(const void* p) {
    uint32_t a;
    asm("{ .reg .u64 t; cvta.to.shared.u64 t, %1; cvt.u32.u64 %0, t; }"
        : "=r"(a) : "l"(p));
    return a;
}
__device__ __forceinline__ void mbar_init(uint32_t a, uint32_t cnt) {
    asm volatile("mbarrier.init.shared.b64 [%0], %1;" :: "r"(a), "r"(cnt) : "memory");
}
__device__ __forceinline__ void mbar_expect(uint32_t a, uint32_t tx) {
    asm volatile("mbarrier.arrive.expect_tx.shared.b64 _, [%0], %1;"
                 :: "r"(a), "r"(tx) : "memory");
}
__device__ __forceinline__ void mbar_arrive(uint32_t a) {
    asm volatile("mbarrier.arrive.shared.b64 _, [%0];" :: "r"(a) : "memory");
}
__device__ __forceinline__ void mbar_wait(uint32_t a, uint32_t parity) {
    asm volatile(
        "{\n\t.reg .pred P;\n\t"
        "W_%=:\n\t"
        "mbarrier.try_wait.parity.shared.b64 P, [%0], %1, 0x989680;\n\t"
        "@!P bra W_%=;\n\t}"
        :: "r"(a), "r"(parity) : "memory");
}
__device__ __forceinline__ void cpbulk(uint32_t dst, const void* src,
                                       uint32_t bytes, uint32_t mbar) {
    asm volatile(
        "cp.async.bulk.shared::cluster.global.mbarrier::complete_tx::bytes "
        "[%0], [%1], %2, [%3];"
        :: "r"(dst), "l"(src), "r"(bytes), "r"(mbar) : "memory");
}
__device__ __forceinline__ void mma_bf16(float* c, uint32_t a0, uint32_t a1,
                                         uint32_t a2, uint32_t a3,
                                         uint32_t b0, uint32_t b1) {
    asm volatile(
        "mma.sync.aligned.m16n8k16.row.col.f32.bf16.bf16.f32 "
        "{%0,%1,%2,%3}, {%4,%5,%6,%7}, {%8,%9}, {%0,%1,%2,%3};"
        : "+f"(c[0]), "+f"(c[1]), "+f"(c[2]), "+f"(c[3])
        : "r"(a0), "r"(a1), "r"(a2), "r"(a3), "r"(b0), "r"(b1));
}
// Fast GELU: tanh formulation with HW MUFU.TANH. Error << bf16 ulp of H.
__device__ __forceinline__ float gelu_fast(float v) {
    float inner = 0.7978845608028654f * v * fmaf(0.044715f, v * v, 1.0f);
    float t;
    asm("tanh.approx.f32 %0, %1;" : "=f"(t) : "f"(inner));
    float hv = 0.5f * v;
    return fmaf(hv, t, hv);
}
// packed fp32 pair ops
__device__ __forceinline__ uint64_t pack2(float lo, float hi) {
    uint64_t d;
    asm("mov.b64 %0, {%1, %2};" : "=l"(d) : "f"(lo), "f"(hi));
    return d;
}
__device__ __forceinline__ void unpack2(uint64_t v, float& lo, float& hi) {
    asm("mov.b64 {%0, %1}, %2;" : "=f"(lo), "=f"(hi) : "l"(v));
}
__device__ __forceinline__ void fma2(uint64_t& d, uint64_t a, uint64_t b) {
    asm("fma.rn.f32x2 %0, %1, %2, %0;" : "+l"(d) : "l"(a), "l"(b));
}
__device__ __forceinline__ uint64_t add2(uint64_t a, uint64_t b) {
    uint64_t d;
    asm("add.rn.f32x2 %0, %1, %2;" : "=l"(d) : "l"(a), "l"(b));
    return d;
}

// ---------------------------------------------------------------------------
// weight prep
// ---------------------------------------------------------------------------
__global__ void prep_w1(const float* __restrict__ src, __nv_bfloat16* __restrict__ dst) {
    int i = blockIdx.x * blockDim.x + threadIdx.x;
    if (i < HID * DIM) {
        int n = i / DIM, k = i - n * DIM;
        int p = (k >> 1) & 7, pos = ((p & 3) << 1) | (p >> 2);
        size_t byte = (size_t)(n >> 7) * 65536 + (size_t)(k >> 4) * 4096
                    + (size_t)(n & 127) * 32 + pos * 4 + (k & 1) * 2;
        *(__nv_bfloat16*)((char*)dst + byte) = __float2bfloat16(src[i]);
    }
}
__global__ void prep_w2(const float* __restrict__ src, __nv_bfloat16* __restrict__ dst) {
    int i = blockIdx.x * blockDim.x + threadIdx.x;
    if (i < DIM * HID) {
        int n = i / HID, k = i - n * HID;
        int p = (k >> 1) & 7, pos = ((p & 3) << 1) | (p >> 2);
        size_t byte = (size_t)((n >> 7) * 16 + (k >> 6)) * 16384
                    + (size_t)((k >> 4) & 3) * 4096
                    + (size_t)(n & 127) * 32 + pos * 4 + (k & 1) * 2;
        *(__nv_bfloat16*)((char*)dst + byte) = __float2bfloat16(src[i]);
    }
}

// ---------------------------------------------------------------------------
// Kernel 1: depthwise 7x7 conv + bias + LayerNorm over W.
// f32x2 math; DIVISION-FREE smem fill (warp=row, lane=col).
// ---------------------------------------------------------------------------
__global__ __launch_bounds__(128) void conv_ln_kernel(
    const float* __restrict__ x, const float* __restrict__ cw,
    const float* __restrict__ cb, const float* __restrict__ g,
    const float* __restrict__ bta, __nv_bfloat16* __restrict__ Y)
{
    __shared__ float s[10 * 262];
    __shared__ float swts[49];
    __shared__ float red[2][4][4];

    const int h0 = blockIdx.x * 4;
    const int c = blockIdx.y, b = blockIdx.z;
    const int tid = threadIdx.x;
    const int w0 = tid * 2;
    const int lane = tid & 31, warp = tid >> 5;

    if (tid < 49) swts[tid] = cw[c * 49 + tid];

    const float* xp = x + ((size_t)(b * DIM + c)) * DIM * DIM;
#pragma unroll
    for (int rr = 0; rr < 3; rr++) {
        const int ro = warp + rr * 4;
        if (ro < 10) {
            const int hh = h0 - 3 + ro;
            const bool hok = (hh >= 0) && (hh < DIM);
            const float* xr = xp + (size_t)hh * DIM;
            float* sr = s + ro * 262;
#pragma unroll
            for (int cc = 0; cc < 9; cc++) {
                const int col = lane + cc * 32;
                if (cc < 8 || col < 262) {
                    const int ww = col - 3;
                    float v = 0.f;
                    if (hok && ww >= 0 && ww < DIM) v = __ldg(xr + ww);
                    sr[col] = v;
                }
            }
        }
    }
    __syncthreads();

    uint64_t wp[49];
#pragma unroll
    for (int i = 0; i < 49; i++) { float w = swts[i]; wp[i] = pack2(w, w); }

    const float cbc = cb[c];
    uint64_t acc[4];
#pragma unroll
    for (int r = 0; r < 4; r++) acc[r] = pack2(cbc, cbc);

#pragma unroll
    for (int ro = 0; ro < 10; ro++) {
        float2 p0 = *(const float2*)&s[ro * 262 + w0];
        float2 p1 = *(const float2*)&s[ro * 262 + w0 + 2];
        float2 p2 = *(const float2*)&s[ro * 262 + w0 + 4];
        float2 p3 = *(const float2*)&s[ro * 262 + w0 + 6];
        float v[8] = {p0.x, p0.y, p1.x, p1.y, p2.x, p2.y, p3.x, p3.y};
        uint64_t vp[7];
#pragma unroll
        for (int kw = 0; kw < 7; kw++) vp[kw] = pack2(v[kw], v[kw + 1]);
#pragma unroll
        for (int r = 0; r < 4; r++) {
            const int kh = ro - r;
            if (kh >= 0 && kh < 7) {
#pragma unroll
                for (int kw = 0; kw < 7; kw++)
                    fma2(acc[r], vp[kw], wp[kh * 7 + kw]);
            }
        }
    }

    float a0[4], a1[4];
#pragma unroll
    for (int r = 0; r < 4; r++) unpack2(acc[r], a0[r], a1[r]);

#pragma unroll
    for (int r = 0; r < 4; r++) {
        float sv = a0[r] + a1[r];
        float sq = a0[r] * a0[r] + a1[r] * a1[r];
#pragma unroll
        for (int o = 16; o; o >>= 1) {
            sv += __shfl_xor_sync(0xffffffffu, sv, o);
            sq += __shfl_xor_sync(0xffffffffu, sq, o);
        }
        if (lane == 0) { red[0][r][warp] = sv; red[1][r][warp] = sq; }
    }
    __syncthreads();

    const float gv0 = g[w0], gv1 = g[w0 + 1];
    const float bv0 = bta[w0], bv1 = bta[w0 + 1];
    const int p = tid & 7, pos = ((p & 3) << 1) | (p >> 2);
    const int j = w0 >> 6, kgl = (w0 >> 4) & 3;
    const size_t mbase = (size_t)(b * DIM + c) * DIM;
#pragma unroll
    for (int r = 0; r < 4; r++) {
        float S  = red[0][r][0] + red[0][r][1] + red[0][r][2] + red[0][r][3];
        float S2 = red[1][r][0] + red[1][r][1] + red[1][r][2] + red[1][r][3];
        float mu  = S * (1.f / 256.f);
        float var = S2 * (1.f / 256.f) - mu * mu;
        float inv = rsqrtf(var + EPS_LN);
        __nv_bfloat162 o;
        o.x = __float2bfloat16((a0[r] - mu) * inv * gv0 + bv0);
        o.y = __float2bfloat16((a1[r] - mu) * inv * gv1 + bv1);
        const size_t m = mbase + h0 + r;
        const size_t byte = (size_t)((m >> 7) * 4 + j) * 16384
                          + kgl * 4096 + (m & 127) * 32 + pos * 4;
        *(__nv_bfloat162*)((char*)Y + byte) = o;
    }
}

// ---------------------------------------------------------------------------
// GEMM1 persistent: H = gelu(Y @ W1^T + b1). 296 CTAs (8 panels x 37 groups).
// Resident 64KB W1 panel + 3 x 16KB A stages. B-fragments double-buffered
// in registers (prefetched across kg and j boundaries — panel is resident).
// ---------------------------------------------------------------------------
__global__ void __launch_bounds__(128, 2) gemm1_persist(
    const __nv_bfloat16* __restrict__ A, const __nv_bfloat16* __restrict__ Bm,
    const float* __restrict__ bias, __nv_bfloat16* __restrict__ C)
{
    constexpr int NGR = 37;
    extern __shared__ char smem[];          // [0,64K) panel, [64K,112K) stages
    __shared__ uint64_t mbar[7];            // full0..2, empty0..2, panel
    const uint32_t sb = smem_u32(smem);
    const uint32_t mb = smem_u32(mbar);

    const int tid = threadIdx.x;
    const int panel = blockIdx.x & 7;
    const int gr = blockIdx.x >> 3;
    const int t0 = (gr * 1024) / NGR, t1 = ((gr + 1) * 1024) / NGR;
    const int n0 = panel * 128;
    const int total = (t1 - t0) * 4;

    if (tid == 0) {
#pragma unroll
        for (int s = 0; s < 3; s++) {
            mbar_init(mb + 8u * s, 1);
            mbar_init(mb + 24u + 8u * s, 128);
        }
        mbar_init(mb + 48u, 1);
    }
    __syncthreads();

    const char* Yb = (const char*)A;
    if (tid == 0) {
        mbar_expect(mb + 48u, 65536u);
        cpbulk(sb, (const char*)Bm + (size_t)panel * 65536, 65536u, mb + 48u);
#pragma unroll
        for (int I = 0; I < 2; I++) {       // fresh stages: no empty wait
            mbar_expect(mb + 8u * I, 16384u);
            cpbulk(sb + 65536u + 16384u * I,
                   Yb + (size_t)(t0 * 4 + I) * 16384, 16384u, mb + 8u * I);
        }
    }
    mbar_wait(mb + 48u, 0);

    const int warp = tid >> 5, lane = tid & 31;
    const int m_w = (warp >> 1) * 64, n_w = (warp & 1) * 64;
    const int r = lane >> 2, tig = lane & 3;
    const int aoff = 65536 + (m_w + r) * 32 + tig * 8;
    const int boff = (n_w + r) * 32 + tig * 8;

    // B-fragment register double buffer; panel is resident so prefetch is
    // unconditional. slab(j, kg) at boff + (j*4 + kg)*4096.
    uint2 bfb[2][8];
#define LOADB(buf, slab) do {                                                 \
    const char* bk_ = smem + boff + (slab) * 4096;                            \
    _Pragma("unroll")                                                         \
    for (int ni_ = 0; ni_ < 8; ni_++)                                         \
        bfb[buf][ni_] = *(const uint2*)(bk_ + ni_ * 256);                     \
} while (0)

    int L = 0;
#pragma unroll 1
    for (int t = t0; t < t1; t++) {
        float acc[4][8][4] = {};
        LOADB(0, 0);
#pragma unroll 1
        for (int j = 0; j < 4; j++, L++) {
            if (tid == 0) {
                const int I = L + 2;
                if (I < total) {
                    const int s = I % 3;
                    if (I >= 3) mbar_wait(mb + 24u + 8u * s, ((I / 3) & 1) ^ 1);
                    mbar_expect(mb + 8u * s, 16384u);
                    cpbulk(sb + 65536u + 16384u * (uint32_t)s,
                           Yb + (size_t)(t0 * 4 + I) * 16384, 16384u, mb + 8u * s);
                }
            }
            const int s = L % 3;
            mbar_wait(mb + 8u * s, (uint32_t)((L / 3) & 1));

            const char* sa = smem + aoff + s * 16384;
#pragma unroll
            for (int kg = 0; kg < 4; kg++) {
                const int cur = kg & 1;
                const int nslab = (j * 4 + kg + 1) & 15;   // next kg (wraps to j+1, or j=0 reload)
                LOADB(cur ^ 1, nslab);
                const char* sk = sa + kg * 4096;
#pragma unroll
                for (int mi = 0; mi < 4; mi++) {
                    uint2 alo = *(const uint2*)(sk + mi * 512);
                    uint2 ahi = *(const uint2*)(sk + mi * 512 + 256);
#pragma unroll
                    for (int ni = 0; ni < 8; ni++)
                        mma_bf16(acc[mi][ni], alo.x, ahi.x, alo.y, ahi.y,
                                 bfb[cur][ni].x, bfb[cur][ni].y);
                }
            }
            mbar_arrive(mb + 24u + 8u * s);
        }

        // epilogue: fast GELU, bf16x2 pair-converts, STG.64 paired stores.
        char* Cb = (char*)C;
#pragma unroll
        for (int q = 0; q < 4; q++) {
            const int ne = n0 + n_w + q * 16 + 2 * tig;   // even-ni column
            const float be0 = __ldg(bias + ne),     be1 = __ldg(bias + ne + 1);
            const float bo0 = __ldg(bias + ne + 8), bo1 = __ldg(bias + ne + 9);
            const size_t base = (size_t)(t * 16 + (ne >> 6)) * 16384
                              + (size_t)((ne >> 4) & 3) * 4096 + tig * 8;
#pragma unroll
            for (int mi = 0; mi < 4; mi++) {
                const int rr = m_w + mi * 16 + r;
                const float* ae = acc[mi][2 * q];
                const float* ao = acc[mi][2 * q + 1];
                __nv_bfloat162 e0 = __floats2bfloat162_rn(
                    gelu_fast(ae[0] + be0), gelu_fast(ae[1] + be1));
                __nv_bfloat162 o0 = __floats2bfloat162_rn(
                    gelu_fast(ao[0] + bo0), gelu_fast(ao[1] + bo1));
                __nv_bfloat162 e1 = __floats2bfloat162_rn(
                    gelu_fast(ae[2] + be0), gelu_fast(ae[3] + be1));
                __nv_bfloat162 o1 = __floats2bfloat162_rn(
                    gelu_fast(ao[2] + bo0), gelu_fast(ao[3] + bo1));
                uint2 lo = make_uint2(*(uint32_t*)&e0, *(uint32_t*)&o0);
                uint2 hi = make_uint2(*(uint32_t*)&e1, *(uint32_t*)&o1);
                *(uint2*)(Cb + base + (size_t)rr * 32)       = lo;
                *(uint2*)(Cb + base + (size_t)(rr + 8) * 32) = hi;
            }
        }
    }
#undef LOADB
}

// ---------------------------------------------------------------------------
// GEMM2: out = H @ W2^T + b2 + x. B-fragments double-buffered within iter.
// ---------------------------------------------------------------------------
__global__ void __launch_bounds__(128, 2) gemm2_bf16(
    const __nv_bfloat16* __restrict__ A, const __nv_bfloat16* __restrict__ Bm,
    const float* __restrict__ bias, const float* __restrict__ xres,
    float* __restrict__ C)
{
    extern __shared__ char smem[];          // 3 x 32KB stages
    __shared__ uint64_t mbar[6];            // full0..2, empty0..2
    const uint32_t sb = smem_u32(smem);
    const uint32_t mb = smem_u32(mbar);

    const int tid = threadIdx.x;
    const int t = blockIdx.y;               // m-tile
    const int panel = blockIdx.x;           // 0..1
    const int m0 = t * 128, n0 = panel * 128;
    const char* Hb = (const char*)A;
    const char* Wb = (const char*)Bm;

    if (tid == 0) {
#pragma unroll
        for (int s = 0; s < 3; s++) {
            mbar_init(mb + 8u * s, 1);
            mbar_init(mb + 24u + 8u * s, 128);
        }
    }
    __syncthreads();

#define ISSUE2(I) do {                                                        \
    const int s_ = (I) % 3;                                                   \
    if ((I) >= 3) mbar_wait(mb + 24u + 8u * s_, (((I) / 3) & 1) ^ 1);         \
    mbar_expect(mb + 8u * s_, 32768u);                                        \
    cpbulk(sb + 32768u * (uint32_t)s_,                                        \
           Hb + (size_t)(t * 16 + (I)) * 16384, 16384u, mb + 8u * s_);        \
    cpbulk(sb + 32768u * (uint32_t)s_ + 16384u,                               \
           Wb + (size_t)(panel * 16 + (I)) * 16384, 16384u, mb + 8u * s_);    \
} while (0)

    if (tid == 0) { ISSUE2(0); ISSUE2(1); }

    const int warp = tid >> 5, lane = tid & 31;
    const int m_w = (warp >> 1) * 64, n_w = (warp & 1) * 64;
    const int r = lane >> 2, tig = lane & 3;
    const int aoff = (m_w + r) * 32 + tig * 8;
    const int boff = 16384 + (n_w + r) * 32 + tig * 8;

    float acc[4][8][4] = {};

#pragma unroll 1
    for (int L = 0; L < 16; L++) {
        if (tid == 0 && L + 2 < 16) ISSUE2(L + 2);
        const int s = L % 3;
        mbar_wait(mb + 8u * s, (uint32_t)((L / 3) & 1));

        const char* st = smem + (size_t)s * 32768;
        uint2 bfb[2][8];
#pragma unroll
        for (int ni = 0; ni < 8; ni++)
            bfb[0][ni] = *(const uint2*)(st + boff + ni * 256);
#pragma unroll
        for (int kg = 0; kg < 4; kg++) {
            const int cur = kg & 1;
            if (kg < 3) {
                const char* bk = st + boff + (kg + 1) * 4096;
#pragma unroll
                for (int ni = 0; ni < 8; ni++)
                    bfb[cur ^ 1][ni] = *(const uint2*)(bk + ni * 256);
            }
            const char* sk = st + aoff + kg * 4096;
#pragma unroll
            for (int mi = 0; mi < 4; mi++) {
                uint2 alo = *(const uint2*)(sk + mi * 512);
                uint2 ahi = *(const uint2*)(sk + mi * 512 + 256);
#pragma unroll
                for (int ni = 0; ni < 8; ni++)
                    mma_bf16(acc[mi][ni], alo.x, ahi.x, alo.y, ahi.y,
                             bfb[cur][ni].x, bfb[cur][ni].y);
            }
        }
        mbar_arrive(mb + 24u + 8u * s);
    }
#undef ISSUE2

    __syncthreads();                        // all bulks done (all 16 waited)
    float* tile = (float*)smem;
#pragma unroll
    for (int ni = 0; ni < 8; ni++) {
        const int n_l = n_w + ni * 8 + 2 * tig;
#pragma unroll
        for (int mi = 0; mi < 4; mi++) {
            const int m_l = m_w + mi * 16 + r;
            tile[n_l * 132 + m_l]           = acc[mi][ni][0];
            tile[(n_l + 1) * 132 + m_l]     = acc[mi][ni][1];
            tile[n_l * 132 + m_l + 8]       = acc[mi][ni][2];
            tile[(n_l + 1) * 132 + m_l + 8] = acc[mi][ni][3];
        }
    }
    __syncthreads();
    const int bb = m0 >> 16, cc = (m0 >> 8) & 255, h0 = m0 & 255;
#pragma unroll
    for (int itr = 0; itr < 32; itr++) {
        const int nl = warp + itr * 4;
        const float bj = __ldg(bias + n0 + nl);
        const uint64_t bjp = pack2(bj, bj);
        size_t base = ((size_t)bb << 24) + ((size_t)(n0 + nl) << 16)
                    + ((size_t)cc << 8) + (size_t)h0 + (size_t)(lane * 4);
        float4 tv = *(float4*)&tile[nl * 132 + lane * 4];
        float4 xv = *(const float4*)&xres[base];
        uint64_t* tp = (uint64_t*)&tv;
        const uint64_t* xp = (const uint64_t*)&xv;
        tp[0] = add2(add2(tp[0], bjp), xp[0]);
        tp[1] = add2(add2(tp[1], bjp), xp[1]);
        *(float4*)&C[base] = tv;
    }
}

// ---------------------------------------------------------------------------
extern "C" void kernel_launch(void* const* d_in, const int* in_sizes, int n_in,
                              void* d_out, int out_size)
{
    (void)in_sizes; (void)n_in; (void)out_size;
    const float* x   = (const float*)d_in[0];
    const float* cw  = (const float*)d_in[1];
    const float* cb  = (const float*)d_in[2];
    const float* g   = (const float*)d_in[3];
    const float* bta = (const float*)d_in[4];
    const float* w1  = (const float*)d_in[5];
    const float* b1  = (const float*)d_in[6];
    const float* w2  = (const float*)d_in[7];
    const float* b2  = (const float*)d_in[8];
    float* out = (float*)d_out;

    __nv_bfloat16 *Y, *H, *W1, *W2;
    cudaGetSymbolAddress((void**)&Y,  g_Y);
    cudaGetSymbolAddress((void**)&H,  g_H);
    cudaGetSymbolAddress((void**)&W1, g_W1);
    cudaGetSymbolAddress((void**)&W2, g_W2);

    const int SMEM_G1 = 114688;  // 64KB panel + 3 x 16KB A stages
    const int SMEM_G2 = 98304;   // 3 x 32KB stages (>= 67.6KB transpose tile)
    cudaFuncSetAttribute(gemm1_persist,
                         cudaFuncAttributeMaxDynamicSharedMemorySize, SMEM_G1);
    cudaFuncSetAttribute(gemm2_bf16,
                         cudaFuncAttributeMaxDynamicSharedMemorySize, SMEM_G2);

    // 0) weights -> bf16 block layouts
    prep_w1<<<(HID * DIM + 255) / 256, 256>>>(w1, W1);
    prep_w2<<<(DIM * HID + 255) / 256, 256>>>(w2, W2);

    // 1) depthwise conv + bias + LayerNorm(W) -> Y (bf16 tile-blocks)
    conv_ln_kernel<<<dim3(DIM / 4, DIM, BATCH), 128>>>(x, cw, cb, g, bta, Y);

    // 2) GEMM1 persistent + fast GELU -> H (bf16 tile-blocks)
    gemm1_persist<<<296, 128, SMEM_G1>>>(Y, W1, b1, H);

    // 3) GEMM2 + bias + transposed residual -> out (fp32)
    gemm2_bf16<<<dim3(2, M_ROWS / 128), 128, SMEM_G2>>>(H, W2, b2, x, out);
}

// round 14
// speedup vs baseline: 2.1756x; 1.0294x over previous
#include <cuda_runtime.h>
#include <cuda_bf16.h>
#include <cstdint>

#define DIM 256
#define BATCH 2
#define M_ROWS (BATCH * DIM * DIM)   // 131072
#define HID (4 * DIM)                // 1024
#define EPS_LN 1e-5f

// Scratch. GEMM operands in TILE-BLOCK layout: 16KB block = (128 rows x 64 k)
// = 4 kg-slabs of 4KB; slab = row*32B; within 32B: 8 bf16-pairs at permuted
// position pos(p)=((p&3)<<1)|(p>>2), p=(k>>1)&7. Blocks are contiguous so a
// whole stage loads with ONE cp.async.bulk.
__device__ __align__(256) __nv_bfloat16 g_Y[(size_t)M_ROWS * DIM];
__device__ __align__(256) __nv_bfloat16 g_H[(size_t)M_ROWS * HID];
__device__ __align__(256) __nv_bfloat16 g_W1[(size_t)HID * DIM];
__device__ __align__(256) __nv_bfloat16 g_W2[(size_t)DIM * HID];

// ---------------------------------------------------------------------------
// helpers
// ---------------------------------------------------------------------------
__device__ __forceinline__ uint32_t smem_u32(const void* p) {
    uint32_t a;
    asm("{ .reg .u64 t; cvta.to.shared.u64 t, %1; cvt.u32.u64 %0, t; }"
        : "=r"(a) : "l"(p));
    return a;
}
__device__ __forceinline__ void mbar_init(uint32_t a, uint32_t cnt) {
    asm volatile("mbarrier.init.shared.b64 [%0], %1;" :: "r"(a), "r"(cnt) : "memory");
}
__device__ __forceinline__ void mbar_expect(uint32_t a, uint32_t tx) {
    asm volatile("mbarrier.arrive.expect_tx.shared.b64 _, [%0], %1;"
                 :: "r"(a), "r"(tx) : "memory");
}
__device__ __forceinline__ void mbar_arrive(uint32_t a) {
    asm volatile("mbarrier.arrive.shared.b64 _, [%0];" :: "r"(a) : "memory");
}
__device__ __forceinline__ void mbar_wait(uint32_t a, uint32_t parity) {
    asm volatile(
        "{\n\t.reg .pred P;\n\t"
        "W_%=:\n\t"
        "mbarrier.try_wait.parity.shared.b64 P, [%0], %1, 0x989680;\n\t"
        "@!P bra W_%=;\n\t}"
        :: "r"(a), "r"(parity) : "memory");
}
__device__ __forceinline__ void cpbulk(uint32_t dst, const void* src,
                                       uint32_t bytes, uint32_t mbar) {
    asm volatile(
        "cp.async.bulk.shared::cluster.global.mbarrier::complete_tx::bytes "
        "[%0], [%1], %2, [%3];"
        :: "r"(dst), "l"(src), "r"(bytes), "r"(mbar) : "memory");
}
__device__ __forceinline__ void mma_bf16(float* c, uint32_t a0, uint32_t a1,
                                         uint32_t a2, uint32_t a3,
                                         uint32_t b0, uint32_t b1) {
    asm volatile(
        "mma.sync.aligned.m16n8k16.row.col.f32.bf16.bf16.f32 "
        "{%0,%1,%2,%3}, {%4,%5,%6,%7}, {%8,%9}, {%0,%1,%2,%3};"
        : "+f"(c[0]), "+f"(c[1]), "+f"(c[2]), "+f"(c[3])
        : "r"(a0), "r"(a1), "r"(a2), "r"(a3), "r"(b0), "r"(b1));
}
// Fast GELU: tanh formulation with HW MUFU.TANH. Error << bf16 ulp of H.
__device__ __forceinline__ float gelu_fast(float v) {
    float inner = 0.7978845608028654f * v * fmaf(0.044715f, v * v, 1.0f);
    float t;
    asm("tanh.approx.f32 %0, %1;" : "=f"(t) : "f"(inner));
    float hv = 0.5f * v;
    return fmaf(hv, t, hv);
}
// packed fp32 pair ops
__device__ __forceinline__ uint64_t pack2(float lo, float hi) {
    uint64_t d;
    asm("mov.b64 %0, {%1, %2};" : "=l"(d) : "f"(lo), "f"(hi));
    return d;
}
__device__ __forceinline__ void unpack2(uint64_t v, float& lo, float& hi) {
    asm("mov.b64 {%0, %1}, %2;" : "=f"(lo), "=f"(hi) : "l"(v));
}
__device__ __forceinline__ void fma2(uint64_t& d, uint64_t a, uint64_t b) {
    asm("fma.rn.f32x2 %0, %1, %2, %0;" : "+l"(d) : "l"(a), "l"(b));
}
__device__ __forceinline__ uint64_t add2(uint64_t a, uint64_t b) {
    uint64_t d;
    asm("add.rn.f32x2 %0, %1, %2;" : "=l"(d) : "l"(a), "l"(b));
    return d;
}

// ---------------------------------------------------------------------------
// weight prep
// ---------------------------------------------------------------------------
__global__ void prep_w1(const float* __restrict__ src, __nv_bfloat16* __restrict__ dst) {
    int i = blockIdx.x * blockDim.x + threadIdx.x;
    if (i < HID * DIM) {
        int n = i / DIM, k = i - n * DIM;
        int p = (k >> 1) & 7, pos = ((p & 3) << 1) | (p >> 2);
        size_t byte = (size_t)(n >> 7) * 65536 + (size_t)(k >> 4) * 4096
                    + (size_t)(n & 127) * 32 + pos * 4 + (k & 1) * 2;
        *(__nv_bfloat16*)((char*)dst + byte) = __float2bfloat16(src[i]);
    }
}
__global__ void prep_w2(const float* __restrict__ src, __nv_bfloat16* __restrict__ dst) {
    int i = blockIdx.x * blockDim.x + threadIdx.x;
    if (i < DIM * HID) {
        int n = i / HID, k = i - n * HID;
        int p = (k >> 1) & 7, pos = ((p & 3) << 1) | (p >> 2);
        size_t byte = (size_t)((n >> 7) * 16 + (k >> 6)) * 16384
                    + (size_t)((k >> 4) & 3) * 4096
                    + (size_t)(n & 127) * 32 + pos * 4 + (k & 1) * 2;
        *(__nv_bfloat16*)((char*)dst + byte) = __float2bfloat16(src[i]);
    }
}

// ---------------------------------------------------------------------------
// Kernel 1: depthwise 7x7 conv + bias + LayerNorm over W.
// v3: 8 output rows per block (halo redundancy 14/8 vs 10/4), 128 threads,
// division-free fill, f32x2 math, weights register-resident.
// ---------------------------------------------------------------------------
__global__ __launch_bounds__(128) void conv_ln_kernel(
    const float* __restrict__ x, const float* __restrict__ cw,
    const float* __restrict__ cb, const float* __restrict__ g,
    const float* __restrict__ bta, __nv_bfloat16* __restrict__ Y)
{
    __shared__ float s[14 * 262];
    __shared__ float swts[49];
    __shared__ float red[2][8][4];

    const int h0 = blockIdx.x * 8;
    const int c = blockIdx.y, b = blockIdx.z;
    const int tid = threadIdx.x;
    const int w0 = tid * 2;
    const int lane = tid & 31, warp = tid >> 5;

    if (tid < 49) swts[tid] = cw[c * 49 + tid];

    const float* xp = x + ((size_t)(b * DIM + c)) * DIM * DIM;
#pragma unroll
    for (int rr = 0; rr < 4; rr++) {
        const int ro = warp + rr * 4;
        if (ro < 14) {
            const int hh = h0 - 3 + ro;
            const bool hok = (hh >= 0) && (hh < DIM);
            const float* xr = xp + (size_t)hh * DIM;
            float* sr = s + ro * 262;
#pragma unroll
            for (int cc = 0; cc < 9; cc++) {
                const int col = lane + cc * 32;
                if (cc < 8 || col < 262) {
                    const int ww = col - 3;
                    float v = 0.f;
                    if (hok && ww >= 0 && ww < DIM) v = __ldg(xr + ww);
                    sr[col] = v;
                }
            }
        }
    }
    __syncthreads();

    uint64_t wp[49];
#pragma unroll
    for (int i = 0; i < 49; i++) { float w = swts[i]; wp[i] = pack2(w, w); }

    const float cbc = cb[c];
    uint64_t acc[8];
#pragma unroll
    for (int r = 0; r < 8; r++) acc[r] = pack2(cbc, cbc);

#pragma unroll
    for (int ro = 0; ro < 14; ro++) {
        float2 p0 = *(const float2*)&s[ro * 262 + w0];
        float2 p1 = *(const float2*)&s[ro * 262 + w0 + 2];
        float2 p2 = *(const float2*)&s[ro * 262 + w0 + 4];
        float2 p3 = *(const float2*)&s[ro * 262 + w0 + 6];
        float v[8] = {p0.x, p0.y, p1.x, p1.y, p2.x, p2.y, p3.x, p3.y};
        uint64_t vp[7];
#pragma unroll
        for (int kw = 0; kw < 7; kw++) vp[kw] = pack2(v[kw], v[kw + 1]);
#pragma unroll
        for (int r = 0; r < 8; r++) {
            const int kh = ro - r;
            if (kh >= 0 && kh < 7) {
#pragma unroll
                for (int kw = 0; kw < 7; kw++)
                    fma2(acc[r], vp[kw], wp[kh * 7 + kw]);
            }
        }
    }

    float a0[8], a1[8];
#pragma unroll
    for (int r = 0; r < 8; r++) unpack2(acc[r], a0[r], a1[r]);

#pragma unroll
    for (int r = 0; r < 8; r++) {
        float sv = a0[r] + a1[r];
        float sq = a0[r] * a0[r] + a1[r] * a1[r];
#pragma unroll
        for (int o = 16; o; o >>= 1) {
            sv += __shfl_xor_sync(0xffffffffu, sv, o);
            sq += __shfl_xor_sync(0xffffffffu, sq, o);
        }
        if (lane == 0) { red[0][r][warp] = sv; red[1][r][warp] = sq; }
    }
    __syncthreads();

    const float gv0 = g[w0], gv1 = g[w0 + 1];
    const float bv0 = bta[w0], bv1 = bta[w0 + 1];
    const int p = tid & 7, pos = ((p & 3) << 1) | (p >> 2);
    const int j = w0 >> 6, kgl = (w0 >> 4) & 3;
    const size_t mbase = (size_t)(b * DIM + c) * DIM;
#pragma unroll
    for (int r = 0; r < 8; r++) {
        float S  = red[0][r][0] + red[0][r][1] + red[0][r][2] + red[0][r][3];
        float S2 = red[1][r][0] + red[1][r][1] + red[1][r][2] + red[1][r][3];
        float mu  = S * (1.f / 256.f);
        float var = S2 * (1.f / 256.f) - mu * mu;
        float inv = rsqrtf(var + EPS_LN);
        __nv_bfloat162 o;
        o.x = __float2bfloat16((a0[r] - mu) * inv * gv0 + bv0);
        o.y = __float2bfloat16((a1[r] - mu) * inv * gv1 + bv1);
        const size_t m = mbase + h0 + r;
        const size_t byte = (size_t)((m >> 7) * 4 + j) * 16384
                          + kgl * 4096 + (m & 127) * 32 + pos * 4;
        *(__nv_bfloat162*)((char*)Y + byte) = o;
    }
}

// ---------------------------------------------------------------------------
// GEMM1 persistent (unchanged from R13): H = gelu(Y @ W1^T + b1).
// ---------------------------------------------------------------------------
__global__ void __launch_bounds__(128, 2) gemm1_persist(
    const __nv_bfloat16* __restrict__ A, const __nv_bfloat16* __restrict__ Bm,
    const float* __restrict__ bias, __nv_bfloat16* __restrict__ C)
{
    constexpr int NGR = 37;
    extern __shared__ char smem[];          // [0,64K) panel, [64K,112K) stages
    __shared__ uint64_t mbar[7];            // full0..2, empty0..2, panel
    const uint32_t sb = smem_u32(smem);
    const uint32_t mb = smem_u32(mbar);

    const int tid = threadIdx.x;
    const int panel = blockIdx.x & 7;
    const int gr = blockIdx.x >> 3;
    const int t0 = (gr * 1024) / NGR, t1 = ((gr + 1) * 1024) / NGR;
    const int n0 = panel * 128;
    const int total = (t1 - t0) * 4;

    if (tid == 0) {
#pragma unroll
        for (int s = 0; s < 3; s++) {
            mbar_init(mb + 8u * s, 1);
            mbar_init(mb + 24u + 8u * s, 128);
        }
        mbar_init(mb + 48u, 1);
    }
    __syncthreads();

    const char* Yb = (const char*)A;
    if (tid == 0) {
        mbar_expect(mb + 48u, 65536u);
        cpbulk(sb, (const char*)Bm + (size_t)panel * 65536, 65536u, mb + 48u);
#pragma unroll
        for (int I = 0; I < 2; I++) {       // fresh stages: no empty wait
            mbar_expect(mb + 8u * I, 16384u);
            cpbulk(sb + 65536u + 16384u * I,
                   Yb + (size_t)(t0 * 4 + I) * 16384, 16384u, mb + 8u * I);
        }
    }
    mbar_wait(mb + 48u, 0);

    const int warp = tid >> 5, lane = tid & 31;
    const int m_w = (warp >> 1) * 64, n_w = (warp & 1) * 64;
    const int r = lane >> 2, tig = lane & 3;
    const int aoff = 65536 + (m_w + r) * 32 + tig * 8;
    const int boff = (n_w + r) * 32 + tig * 8;

    uint2 bfb[2][8];
#define LOADB(buf, slab) do {                                                 \
    const char* bk_ = smem + boff + (slab) * 4096;                            \
    _Pragma("unroll")                                                         \
    for (int ni_ = 0; ni_ < 8; ni_++)                                         \
        bfb[buf][ni_] = *(const uint2*)(bk_ + ni_ * 256);                     \
} while (0)

    int L = 0;
#pragma unroll 1
    for (int t = t0; t < t1; t++) {
        float acc[4][8][4] = {};
        LOADB(0, 0);
#pragma unroll 1
        for (int j = 0; j < 4; j++, L++) {
            if (tid == 0) {
                const int I = L + 2;
                if (I < total) {
                    const int s = I % 3;
                    if (I >= 3) mbar_wait(mb + 24u + 8u * s, ((I / 3) & 1) ^ 1);
                    mbar_expect(mb + 8u * s, 16384u);
                    cpbulk(sb + 65536u + 16384u * (uint32_t)s,
                           Yb + (size_t)(t0 * 4 + I) * 16384, 16384u, mb + 8u * s);
                }
            }
            const int s = L % 3;
            mbar_wait(mb + 8u * s, (uint32_t)((L / 3) & 1));

            const char* sa = smem + aoff + s * 16384;
#pragma unroll
            for (int kg = 0; kg < 4; kg++) {
                const int cur = kg & 1;
                const int nslab = (j * 4 + kg + 1) & 15;
                LOADB(cur ^ 1, nslab);
                const char* sk = sa + kg * 4096;
#pragma unroll
                for (int mi = 0; mi < 4; mi++) {
                    uint2 alo = *(const uint2*)(sk + mi * 512);
                    uint2 ahi = *(const uint2*)(sk + mi * 512 + 256);
#pragma unroll
                    for (int ni = 0; ni < 8; ni++)
                        mma_bf16(acc[mi][ni], alo.x, ahi.x, alo.y, ahi.y,
                                 bfb[cur][ni].x, bfb[cur][ni].y);
                }
            }
            mbar_arrive(mb + 24u + 8u * s);
        }

        // epilogue: fast GELU, bf16x2 pair-converts, STG.64 paired stores.
        char* Cb = (char*)C;
#pragma unroll
        for (int q = 0; q < 4; q++) {
            const int ne = n0 + n_w + q * 16 + 2 * tig;   // even-ni column
            const float be0 = __ldg(bias + ne),     be1 = __ldg(bias + ne + 1);
            const float bo0 = __ldg(bias + ne + 8), bo1 = __ldg(bias + ne + 9);
            const size_t base = (size_t)(t * 16 + (ne >> 6)) * 16384
                              + (size_t)((ne >> 4) & 3) * 4096 + tig * 8;
#pragma unroll
            for (int mi = 0; mi < 4; mi++) {
                const int rr = m_w + mi * 16 + r;
                const float* ae = acc[mi][2 * q];
                const float* ao = acc[mi][2 * q + 1];
                __nv_bfloat162 e0 = __floats2bfloat162_rn(
                    gelu_fast(ae[0] + be0), gelu_fast(ae[1] + be1));
                __nv_bfloat162 o0 = __floats2bfloat162_rn(
                    gelu_fast(ao[0] + bo0), gelu_fast(ao[1] + bo1));
                __nv_bfloat162 e1 = __floats2bfloat162_rn(
                    gelu_fast(ae[2] + be0), gelu_fast(ae[3] + be1));
                __nv_bfloat162 o1 = __floats2bfloat162_rn(
                    gelu_fast(ao[2] + bo0), gelu_fast(ao[3] + bo1));
                uint2 lo = make_uint2(*(uint32_t*)&e0, *(uint32_t*)&o0);
                uint2 hi = make_uint2(*(uint32_t*)&e1, *(uint32_t*)&o1);
                *(uint2*)(Cb + base + (size_t)rr * 32)       = lo;
                *(uint2*)(Cb + base + (size_t)(rr + 8) * 32) = hi;
            }
        }
    }
#undef LOADB
}

// ---------------------------------------------------------------------------
// GEMM2 (unchanged from R13): out = H @ W2^T + b2 + x.
// ---------------------------------------------------------------------------
__global__ void __launch_bounds__(128, 2) gemm2_bf16(
    const __nv_bfloat16* __restrict__ A, const __nv_bfloat16* __restrict__ Bm,
    const float* __restrict__ bias, const float* __restrict__ xres,
    float* __restrict__ C)
{
    extern __shared__ char smem[];          // 3 x 32KB stages
    __shared__ uint64_t mbar[6];            // full0..2, empty0..2
    const uint32_t sb = smem_u32(smem);
    const uint32_t mb = smem_u32(mbar);

    const int tid = threadIdx.x;
    const int t = blockIdx.y;               // m-tile
    const int panel = blockIdx.x;           // 0..1
    const int m0 = t * 128, n0 = panel * 128;
    const char* Hb = (const char*)A;
    const char* Wb = (const char*)Bm;

    if (tid == 0) {
#pragma unroll
        for (int s = 0; s < 3; s++) {
            mbar_init(mb + 8u * s, 1);
            mbar_init(mb + 24u + 8u * s, 128);
        }
    }
    __syncthreads();

#define ISSUE2(I) do {                                                        \
    const int s_ = (I) % 3;                                                   \
    if ((I) >= 3) mbar_wait(mb + 24u + 8u * s_, (((I) / 3) & 1) ^ 1);         \
    mbar_expect(mb + 8u * s_, 32768u);                                        \
    cpbulk(sb + 32768u * (uint32_t)s_,                                        \
           Hb + (size_t)(t * 16 + (I)) * 16384, 16384u, mb + 8u * s_);        \
    cpbulk(sb + 32768u * (uint32_t)s_ + 16384u,                               \
           Wb + (size_t)(panel * 16 + (I)) * 16384, 16384u, mb + 8u * s_);    \
} while (0)

    if (tid == 0) { ISSUE2(0); ISSUE2(1); }

    const int warp = tid >> 5, lane = tid & 31;
    const int m_w = (warp >> 1) * 64, n_w = (warp & 1) * 64;
    const int r = lane >> 2, tig = lane & 3;
    const int aoff = (m_w + r) * 32 + tig * 8;
    const int boff = 16384 + (n_w + r) * 32 + tig * 8;

    float acc[4][8][4] = {};

#pragma unroll 1
    for (int L = 0; L < 16; L++) {
        if (tid == 0 && L + 2 < 16) ISSUE2(L + 2);
        const int s = L % 3;
        mbar_wait(mb + 8u * s, (uint32_t)((L / 3) & 1));

        const char* st = smem + (size_t)s * 32768;
        uint2 bfb[2][8];
#pragma unroll
        for (int ni = 0; ni < 8; ni++)
            bfb[0][ni] = *(const uint2*)(st + boff + ni * 256);
#pragma unroll
        for (int kg = 0; kg < 4; kg++) {
            const int cur = kg & 1;
            if (kg < 3) {
                const char* bk = st + boff + (kg + 1) * 4096;
#pragma unroll
                for (int ni = 0; ni < 8; ni++)
                    bfb[cur ^ 1][ni] = *(const uint2*)(bk + ni * 256);
            }
            const char* sk = st + aoff + kg * 4096;
#pragma unroll
            for (int mi = 0; mi < 4; mi++) {
                uint2 alo = *(const uint2*)(sk + mi * 512);
                uint2 ahi = *(const uint2*)(sk + mi * 512 + 256);
#pragma unroll
                for (int ni = 0; ni < 8; ni++)
                    mma_bf16(acc[mi][ni], alo.x, ahi.x, alo.y, ahi.y,
                             bfb[cur][ni].x, bfb[cur][ni].y);
            }
        }
        mbar_arrive(mb + 24u + 8u * s);
    }
#undef ISSUE2

    __syncthreads();                        // all bulks done (all 16 waited)
    float* tile = (float*)smem;
#pragma unroll
    for (int ni = 0; ni < 8; ni++) {
        const int n_l = n_w + ni * 8 + 2 * tig;
#pragma unroll
        for (int mi = 0; mi < 4; mi++) {
            const int m_l = m_w + mi * 16 + r;
            tile[n_l * 132 + m_l]           = acc[mi][ni][0];
            tile[(n_l + 1) * 132 + m_l]     = acc[mi][ni][1];
            tile[n_l * 132 + m_l + 8]       = acc[mi][ni][2];
            tile[(n_l + 1) * 132 + m_l + 8] = acc[mi][ni][3];
        }
    }
    __syncthreads();
    const int bb = m0 >> 16, cc = (m0 >> 8) & 255, h0 = m0 & 255;
#pragma unroll
    for (int itr = 0; itr < 32; itr++) {
        const int nl = warp + itr * 4;
        const float bj = __ldg(bias + n0 + nl);
        const uint64_t bjp = pack2(bj, bj);
        size_t base = ((size_t)bb << 24) + ((size_t)(n0 + nl) << 16)
                    + ((size_t)cc << 8) + (size_t)h0 + (size_t)(lane * 4);
        float4 tv = *(float4*)&tile[nl * 132 + lane * 4];
        float4 xv = *(const float4*)&xres[base];
        uint64_t* tp = (uint64_t*)&tv;
        const uint64_t* xp = (const uint64_t*)&xv;
        tp[0] = add2(add2(tp[0], bjp), xp[0]);
        tp[1] = add2(add2(tp[1], bjp), xp[1]);
        *(float4*)&C[base] = tv;
    }
}

// ---------------------------------------------------------------------------
extern "C" void kernel_launch(void* const* d_in, const int* in_sizes, int n_in,
                              void* d_out, int out_size)
{
    (void)in_sizes; (void)n_in; (void)out_size;
    const float* x   = (const float*)d_in[0];
    const float* cw  = (const float*)d_in[1];
    const float* cb  = (const float*)d_in[2];
    const float* g   = (const float*)d_in[3];
    const float* bta = (const float*)d_in[4];
    const float* w1  = (const float*)d_in[5];
    const float* b1  = (const float*)d_in[6];
    const float* w2  = (const float*)d_in[7];
    const float* b2  = (const float*)d_in[8];
    float* out = (float*)d_out;

    __nv_bfloat16 *Y, *H, *W1, *W2;
    cudaGetSymbolAddress((void**)&Y,  g_Y);
    cudaGetSymbolAddress((void**)&H,  g_H);
    cudaGetSymbolAddress((void**)&W1, g_W1);
    cudaGetSymbolAddress((void**)&W2, g_W2);

    const int SMEM_G1 = 114688;  // 64KB panel + 3 x 16KB A stages
    const int SMEM_G2 = 98304;   // 3 x 32KB stages (>= 67.6KB transpose tile)
    cudaFuncSetAttribute(gemm1_persist,
                         cudaFuncAttributeMaxDynamicSharedMemorySize, SMEM_G1);
    cudaFuncSetAttribute(gemm2_bf16,
                         cudaFuncAttributeMaxDynamicSharedMemorySize, SMEM_G2);

    // 0) weights -> bf16 block layouts
    prep_w1<<<(HID * DIM + 255) / 256, 256>>>(w1, W1);
    prep_w2<<<(DIM * HID + 255) / 256, 256>>>(w2, W2);

    // 1) depthwise conv + bias + LayerNorm(W) -> Y (bf16 tile-blocks)
    conv_ln_kernel<<<dim3(DIM / 8, DIM, BATCH), 128>>>(x, cw, cb, g, bta, Y);

    // 2) GEMM1 persistent + fast GELU -> H (bf16 tile-blocks)
    gemm1_persist<<<296, 128, SMEM_G1>>>(Y, W1, b1, H);

    // 3) GEMM2 + bias + transposed residual -> out (fp32)
    gemm2_bf16<<<dim3(2, M_ROWS / 128), 128, SMEM_G2>>>(H, W2, b2, x, out);
}

// round 15
// speedup vs baseline: 2.2739x; 1.0452x over previous
#include <cuda_runtime.h>
#include <cuda_bf16.h>
#include <cstdint>

#define DIM 256
#define BATCH 2
#define M_ROWS (BATCH * DIM * DIM)   // 131072
#define HID (4 * DIM)                // 1024
#define EPS_LN 1e-5f

// Scratch. GEMM operands in TILE-BLOCK layout: 16KB block = (128 rows x 64 k)
// = 4 kg-slabs of 4KB; slab = row*32B; within 32B: 8 bf16-pairs at permuted
// position pos(p)=((p&3)<<1)|(p>>2), p=(k>>1)&7. Blocks are contiguous so a
// whole stage loads with ONE cp.async.bulk.
__device__ __align__(256) __nv_bfloat16 g_Y[(size_t)M_ROWS * DIM];
__device__ __align__(256) __nv_bfloat16 g_H[(size_t)M_ROWS * HID];
__device__ __align__(256) __nv_bfloat16 g_W1[(size_t)HID * DIM];
__device__ __align__(256) __nv_bfloat16 g_W2[(size_t)DIM * HID];

// ---------------------------------------------------------------------------
// helpers
// ---------------------------------------------------------------------------
__device__ __forceinline__ uint32_t smem_u32(const void* p) {
    uint32_t a;
    asm("{ .reg .u64 t; cvta.to.shared.u64 t, %1; cvt.u32.u64 %0, t; }"
        : "=r"(a) : "l"(p));
    return a;
}
__device__ __forceinline__ void mbar_init(uint32_t a, uint32_t cnt) {
    asm volatile("mbarrier.init.shared.b64 [%0], %1;" :: "r"(a), "r"(cnt) : "memory");
}
__device__ __forceinline__ void mbar_expect(uint32_t a, uint32_t tx) {
    asm volatile("mbarrier.arrive.expect_tx.shared.b64 _, [%0], %1;"
                 :: "r"(a), "r"(tx) : "memory");
}
__device__ __forceinline__ void mbar_arrive(uint32_t a) {
    asm volatile("mbarrier.arrive.shared.b64 _, [%0];" :: "r"(a) : "memory");
}
__device__ __forceinline__ void mbar_wait(uint32_t a, uint32_t parity) {
    asm volatile(
        "{\n\t.reg .pred P;\n\t"
        "W_%=:\n\t"
        "mbarrier.try_wait.parity.shared.b64 P, [%0], %1, 0x989680;\n\t"
        "@!P bra W_%=;\n\t}"
        :: "r"(a), "r"(parity) : "memory");
}
__device__ __forceinline__ void cpbulk(uint32_t dst, const void* src,
                                       uint32_t bytes, uint32_t mbar) {
    asm volatile(
        "cp.async.bulk.shared::cluster.global.mbarrier::complete_tx::bytes "
        "[%0], [%1], %2, [%3];"
        :: "r"(dst), "l"(src), "r"(bytes), "r"(mbar) : "memory");
}
__device__ __forceinline__ void mma_bf16(float* c, uint32_t a0, uint32_t a1,
                                         uint32_t a2, uint32_t a3,
                                         uint32_t b0, uint32_t b1) {
    asm volatile(
        "mma.sync.aligned.m16n8k16.row.col.f32.bf16.bf16.f32 "
        "{%0,%1,%2,%3}, {%4,%5,%6,%7}, {%8,%9}, {%0,%1,%2,%3};"
        : "+f"(c[0]), "+f"(c[1]), "+f"(c[2]), "+f"(c[3])
        : "r"(a0), "r"(a1), "r"(a2), "r"(a3), "r"(b0), "r"(b1));
}
// Fast GELU: tanh formulation with HW MUFU.TANH. Error << bf16 ulp of H.
__device__ __forceinline__ float gelu_fast(float v) {
    float inner = 0.7978845608028654f * v * fmaf(0.044715f, v * v, 1.0f);
    float t;
    asm("tanh.approx.f32 %0, %1;" : "=f"(t) : "f"(inner));
    float hv = 0.5f * v;
    return fmaf(hv, t, hv);
}
// packed fp32 pair ops
__device__ __forceinline__ uint64_t pack2(float lo, float hi) {
    uint64_t d;
    asm("mov.b64 %0, {%1, %2};" : "=l"(d) : "f"(lo), "f"(hi));
    return d;
}
__device__ __forceinline__ void unpack2(uint64_t v, float& lo, float& hi) {
    asm("mov.b64 {%0, %1}, %2;" : "=f"(lo), "=f"(hi) : "l"(v));
}
__device__ __forceinline__ void fma2(uint64_t& d, uint64_t a, uint64_t b) {
    asm("fma.rn.f32x2 %0, %1, %2, %0;" : "+l"(d) : "l"(a), "l"(b));
}
__device__ __forceinline__ uint64_t add2(uint64_t a, uint64_t b) {
    uint64_t d;
    asm("add.rn.f32x2 %0, %1, %2;" : "=l"(d) : "l"(a), "l"(b));
    return d;
}

// ---------------------------------------------------------------------------
// Kernel 1: depthwise 7x7 conv + bias + LayerNorm over W, 16-row blocks,
// PLUS fused weight prep on the z==BATCH grid slice (hides under conv).
// ---------------------------------------------------------------------------
__global__ __launch_bounds__(128) void conv_ln_prep_kernel(
    const float* __restrict__ x, const float* __restrict__ cw,
    const float* __restrict__ cb, const float* __restrict__ g,
    const float* __restrict__ bta, __nv_bfloat16* __restrict__ Y,
    const float* __restrict__ w1, const float* __restrict__ w2,
    __nv_bfloat16* __restrict__ W1, __nv_bfloat16* __restrict__ W2)
{
    const int tid = threadIdx.x;
    const int bz = blockIdx.z;

    if (bz == BATCH) {
        // ---- weight prep: 4096 blocks x 128 elems = 524288 = |w1| + |w2| ----
        const int i = (blockIdx.x + blockIdx.y * 16) * 128 + tid;
        if (i < HID * DIM) {
            const int n = i / DIM, k = i - n * DIM;
            const int p = (k >> 1) & 7, pos = ((p & 3) << 1) | (p >> 2);
            const size_t byte = (size_t)(n >> 7) * 65536 + (size_t)(k >> 4) * 4096
                              + (size_t)(n & 127) * 32 + pos * 4 + (k & 1) * 2;
            *(__nv_bfloat16*)((char*)W1 + byte) = __float2bfloat16(w1[i]);
        } else {
            const int i2 = i - HID * DIM;
            const int n = i2 / HID, k = i2 - n * HID;
            const int p = (k >> 1) & 7, pos = ((p & 3) << 1) | (p >> 2);
            const size_t byte = (size_t)((n >> 7) * 16 + (k >> 6)) * 16384
                              + (size_t)((k >> 4) & 3) * 4096
                              + (size_t)(n & 127) * 32 + pos * 4 + (k & 1) * 2;
            *(__nv_bfloat16*)((char*)W2 + byte) = __float2bfloat16(w2[i2]);
        }
        return;
    }

    __shared__ float s[22 * 262];
    __shared__ float swts[49];
    __shared__ float red[2][16][4];

    const int h0 = blockIdx.x * 16;
    const int c = blockIdx.y, b = bz;
    const int w0 = tid * 2;
    const int lane = tid & 31, warp = tid >> 5;

    if (tid < 49) swts[tid] = cw[c * 49 + tid];

    const float* xp = x + ((size_t)(b * DIM + c)) * DIM * DIM;
#pragma unroll
    for (int rr = 0; rr < 6; rr++) {
        const int ro = warp + rr * 4;
        if (ro < 22) {
            const int hh = h0 - 3 + ro;
            const bool hok = (hh >= 0) && (hh < DIM);
            const float* xr = xp + (size_t)hh * DIM;
            float* sr = s + ro * 262;
#pragma unroll
            for (int cc = 0; cc < 9; cc++) {
                const int col = lane + cc * 32;
                if (cc < 8 || col < 262) {
                    const int ww = col - 3;
                    float v = 0.f;
                    if (hok && ww >= 0 && ww < DIM) v = __ldg(xr + ww);
                    sr[col] = v;
                }
            }
        }
    }
    __syncthreads();

    uint64_t wp[49];
#pragma unroll
    for (int i = 0; i < 49; i++) { float w = swts[i]; wp[i] = pack2(w, w); }

    const float cbc = cb[c];
    uint64_t acc[16];
#pragma unroll
    for (int r = 0; r < 16; r++) acc[r] = pack2(cbc, cbc);

#pragma unroll
    for (int ro = 0; ro < 22; ro++) {
        float2 p0 = *(const float2*)&s[ro * 262 + w0];
        float2 p1 = *(const float2*)&s[ro * 262 + w0 + 2];
        float2 p2 = *(const float2*)&s[ro * 262 + w0 + 4];
        float2 p3 = *(const float2*)&s[ro * 262 + w0 + 6];
        float v[8] = {p0.x, p0.y, p1.x, p1.y, p2.x, p2.y, p3.x, p3.y};
        uint64_t vp[7];
#pragma unroll
        for (int kw = 0; kw < 7; kw++) vp[kw] = pack2(v[kw], v[kw + 1]);
#pragma unroll
        for (int r = 0; r < 16; r++) {
            const int kh = ro - r;
            if (kh >= 0 && kh < 7) {
#pragma unroll
                for (int kw = 0; kw < 7; kw++)
                    fma2(acc[r], vp[kw], wp[kh * 7 + kw]);
            }
        }
    }

#pragma unroll
    for (int r = 0; r < 16; r++) {
        float a0, a1;
        unpack2(acc[r], a0, a1);
        float sv = a0 + a1;
        float sq = a0 * a0 + a1 * a1;
#pragma unroll
        for (int o = 16; o; o >>= 1) {
            sv += __shfl_xor_sync(0xffffffffu, sv, o);
            sq += __shfl_xor_sync(0xffffffffu, sq, o);
        }
        if (lane == 0) { red[0][r][warp] = sv; red[1][r][warp] = sq; }
    }
    __syncthreads();

    const float gv0 = g[w0], gv1 = g[w0 + 1];
    const float bv0 = bta[w0], bv1 = bta[w0 + 1];
    const int p = tid & 7, pos = ((p & 3) << 1) | (p >> 2);
    const int j = w0 >> 6, kgl = (w0 >> 4) & 3;
    const size_t mbase = (size_t)(b * DIM + c) * DIM;
#pragma unroll
    for (int r = 0; r < 16; r++) {
        float a0, a1;
        unpack2(acc[r], a0, a1);
        float S  = red[0][r][0] + red[0][r][1] + red[0][r][2] + red[0][r][3];
        float S2 = red[1][r][0] + red[1][r][1] + red[1][r][2] + red[1][r][3];
        float mu  = S * (1.f / 256.f);
        float var = S2 * (1.f / 256.f) - mu * mu;
        float inv = rsqrtf(var + EPS_LN);
        __nv_bfloat162 o;
        o.x = __float2bfloat16((a0 - mu) * inv * gv0 + bv0);
        o.y = __float2bfloat16((a1 - mu) * inv * gv1 + bv1);
        const size_t m = mbase + h0 + r;
        const size_t byte = (size_t)((m >> 7) * 4 + j) * 16384
                          + kgl * 4096 + (m & 127) * 32 + pos * 4;
        *(__nv_bfloat162*)((char*)Y + byte) = o;
    }
}

// ---------------------------------------------------------------------------
// GEMM1 persistent (frozen, R13): H = gelu(Y @ W1^T + b1).
// ---------------------------------------------------------------------------
__global__ void __launch_bounds__(128, 2) gemm1_persist(
    const __nv_bfloat16* __restrict__ A, const __nv_bfloat16* __restrict__ Bm,
    const float* __restrict__ bias, __nv_bfloat16* __restrict__ C)
{
    constexpr int NGR = 37;
    extern __shared__ char smem[];          // [0,64K) panel, [64K,112K) stages
    __shared__ uint64_t mbar[7];            // full0..2, empty0..2, panel
    const uint32_t sb = smem_u32(smem);
    const uint32_t mb = smem_u32(mbar);

    const int tid = threadIdx.x;
    const int panel = blockIdx.x & 7;
    const int gr = blockIdx.x >> 3;
    const int t0 = (gr * 1024) / NGR, t1 = ((gr + 1) * 1024) / NGR;
    const int n0 = panel * 128;
    const int total = (t1 - t0) * 4;

    if (tid == 0) {
#pragma unroll
        for (int s = 0; s < 3; s++) {
            mbar_init(mb + 8u * s, 1);
            mbar_init(mb + 24u + 8u * s, 128);
        }
        mbar_init(mb + 48u, 1);
    }
    __syncthreads();

    const char* Yb = (const char*)A;
    if (tid == 0) {
        mbar_expect(mb + 48u, 65536u);
        cpbulk(sb, (const char*)Bm + (size_t)panel * 65536, 65536u, mb + 48u);
#pragma unroll
        for (int I = 0; I < 2; I++) {       // fresh stages: no empty wait
            mbar_expect(mb + 8u * I, 16384u);
            cpbulk(sb + 65536u + 16384u * I,
                   Yb + (size_t)(t0 * 4 + I) * 16384, 16384u, mb + 8u * I);
        }
    }
    mbar_wait(mb + 48u, 0);

    const int warp = tid >> 5, lane = tid & 31;
    const int m_w = (warp >> 1) * 64, n_w = (warp & 1) * 64;
    const int r = lane >> 2, tig = lane & 3;
    const int aoff = 65536 + (m_w + r) * 32 + tig * 8;
    const int boff = (n_w + r) * 32 + tig * 8;

    uint2 bfb[2][8];
#define LOADB(buf, slab) do {                                                 \
    const char* bk_ = smem + boff + (slab) * 4096;                            \
    _Pragma("unroll")                                                         \
    for (int ni_ = 0; ni_ < 8; ni_++)                                         \
        bfb[buf][ni_] = *(const uint2*)(bk_ + ni_ * 256);                     \
} while (0)

    int L = 0;
#pragma unroll 1
    for (int t = t0; t < t1; t++) {
        float acc[4][8][4] = {};
        LOADB(0, 0);
#pragma unroll 1
        for (int j = 0; j < 4; j++, L++) {
            if (tid == 0) {
                const int I = L + 2;
                if (I < total) {
                    const int s = I % 3;
                    if (I >= 3) mbar_wait(mb + 24u + 8u * s, ((I / 3) & 1) ^ 1);
                    mbar_expect(mb + 8u * s, 16384u);
                    cpbulk(sb + 65536u + 16384u * (uint32_t)s,
                           Yb + (size_t)(t0 * 4 + I) * 16384, 16384u, mb + 8u * s);
                }
            }
            const int s = L % 3;
            mbar_wait(mb + 8u * s, (uint32_t)((L / 3) & 1));

            const char* sa = smem + aoff + s * 16384;
#pragma unroll
            for (int kg = 0; kg < 4; kg++) {
                const int cur = kg & 1;
                const int nslab = (j * 4 + kg + 1) & 15;
                LOADB(cur ^ 1, nslab);
                const char* sk = sa + kg * 4096;
#pragma unroll
                for (int mi = 0; mi < 4; mi++) {
                    uint2 alo = *(const uint2*)(sk + mi * 512);
                    uint2 ahi = *(const uint2*)(sk + mi * 512 + 256);
#pragma unroll
                    for (int ni = 0; ni < 8; ni++)
                        mma_bf16(acc[mi][ni], alo.x, ahi.x, alo.y, ahi.y,
                                 bfb[cur][ni].x, bfb[cur][ni].y);
                }
            }
            mbar_arrive(mb + 24u + 8u * s);
        }

        // epilogue: fast GELU, bf16x2 pair-converts, STG.64 paired stores.
        char* Cb = (char*)C;
#pragma unroll
        for (int q = 0; q < 4; q++) {
            const int ne = n0 + n_w + q * 16 + 2 * tig;   // even-ni column
            const float be0 = __ldg(bias + ne),     be1 = __ldg(bias + ne + 1);
            const float bo0 = __ldg(bias + ne + 8), bo1 = __ldg(bias + ne + 9);
            const size_t base = (size_t)(t * 16 + (ne >> 6)) * 16384
                              + (size_t)((ne >> 4) & 3) * 4096 + tig * 8;
#pragma unroll
            for (int mi = 0; mi < 4; mi++) {
                const int rr = m_w + mi * 16 + r;
                const float* ae = acc[mi][2 * q];
                const float* ao = acc[mi][2 * q + 1];
                __nv_bfloat162 e0 = __floats2bfloat162_rn(
                    gelu_fast(ae[0] + be0), gelu_fast(ae[1] + be1));
                __nv_bfloat162 o0 = __floats2bfloat162_rn(
                    gelu_fast(ao[0] + bo0), gelu_fast(ao[1] + bo1));
                __nv_bfloat162 e1 = __floats2bfloat162_rn(
                    gelu_fast(ae[2] + be0), gelu_fast(ae[3] + be1));
                __nv_bfloat162 o1 = __floats2bfloat162_rn(
                    gelu_fast(ao[2] + bo0), gelu_fast(ao[3] + bo1));
                uint2 lo = make_uint2(*(uint32_t*)&e0, *(uint32_t*)&o0);
                uint2 hi = make_uint2(*(uint32_t*)&e1, *(uint32_t*)&o1);
                *(uint2*)(Cb + base + (size_t)rr * 32)       = lo;
                *(uint2*)(Cb + base + (size_t)(rr + 8) * 32) = hi;
            }
        }
    }
#undef LOADB
}

// ---------------------------------------------------------------------------
// GEMM2 (frozen, R13): out = H @ W2^T + b2 + x.
// ---------------------------------------------------------------------------
__global__ void __launch_bounds__(128, 2) gemm2_bf16(
    const __nv_bfloat16* __restrict__ A, const __nv_bfloat16* __restrict__ Bm,
    const float* __restrict__ bias, const float* __restrict__ xres,
    float* __restrict__ C)
{
    extern __shared__ char smem[];          // 3 x 32KB stages
    __shared__ uint64_t mbar[6];            // full0..2, empty0..2
    const uint32_t sb = smem_u32(smem);
    const uint32_t mb = smem_u32(mbar);

    const int tid = threadIdx.x;
    const int t = blockIdx.y;               // m-tile
    const int panel = blockIdx.x;           // 0..1
    const int m0 = t * 128, n0 = panel * 128;
    const char* Hb = (const char*)A;
    const char* Wb = (const char*)Bm;

    if (tid == 0) {
#pragma unroll
        for (int s = 0; s < 3; s++) {
            mbar_init(mb + 8u * s, 1);
            mbar_init(mb + 24u + 8u * s, 128);
        }
    }
    __syncthreads();

#define ISSUE2(I) do {                                                        \
    const int s_ = (I) % 3;                                                   \
    if ((I) >= 3) mbar_wait(mb + 24u + 8u * s_, (((I) / 3) & 1) ^ 1);         \
    mbar_expect(mb + 8u * s_, 32768u);                                        \
    cpbulk(sb + 32768u * (uint32_t)s_,                                        \
           Hb + (size_t)(t * 16 + (I)) * 16384, 16384u, mb + 8u * s_);        \
    cpbulk(sb + 32768u * (uint32_t)s_ + 16384u,                               \
           Wb + (size_t)(panel * 16 + (I)) * 16384, 16384u, mb + 8u * s_);    \
} while (0)

    if (tid == 0) { ISSUE2(0); ISSUE2(1); }

    const int warp = tid >> 5, lane = tid & 31;
    const int m_w = (warp >> 1) * 64, n_w = (warp & 1) * 64;
    const int r = lane >> 2, tig = lane & 3;
    const int aoff = (m_w + r) * 32 + tig * 8;
    const int boff = 16384 + (n_w + r) * 32 + tig * 8;

    float acc[4][8][4] = {};

#pragma unroll 1
    for (int L = 0; L < 16; L++) {
        if (tid == 0 && L + 2 < 16) ISSUE2(L + 2);
        const int s = L % 3;
        mbar_wait(mb + 8u * s, (uint32_t)((L / 3) & 1));

        const char* st = smem + (size_t)s * 32768;
        uint2 bfb[2][8];
#pragma unroll
        for (int ni = 0; ni < 8; ni++)
            bfb[0][ni] = *(const uint2*)(st + boff + ni * 256);
#pragma unroll
        for (int kg = 0; kg < 4; kg++) {
            const int cur = kg & 1;
            if (kg < 3) {
                const char* bk = st + boff + (kg + 1) * 4096;
#pragma unroll
                for (int ni = 0; ni < 8; ni++)
                    bfb[cur ^ 1][ni] = *(const uint2*)(bk + ni * 256);
            }
            const char* sk = st + aoff + kg * 4096;
#pragma unroll
            for (int mi = 0; mi < 4; mi++) {
                uint2 alo = *(const uint2*)(sk + mi * 512);
                uint2 ahi = *(const uint2*)(sk + mi * 512 + 256);
#pragma unroll
                for (int ni = 0; ni < 8; ni++)
                    mma_bf16(acc[mi][ni], alo.x, ahi.x, alo.y, ahi.y,
                             bfb[cur][ni].x, bfb[cur][ni].y);
            }
        }
        mbar_arrive(mb + 24u + 8u * s);
    }
#undef ISSUE2

    __syncthreads();                        // all bulks done (all 16 waited)
    float* tile = (float*)smem;
#pragma unroll
    for (int ni = 0; ni < 8; ni++) {
        const int n_l = n_w + ni * 8 + 2 * tig;
#pragma unroll
        for (int mi = 0; mi < 4; mi++) {
            const int m_l = m_w + mi * 16 + r;
            tile[n_l * 132 + m_l]           = acc[mi][ni][0];
            tile[(n_l + 1) * 132 + m_l]     = acc[mi][ni][1];
            tile[n_l * 132 + m_l + 8]       = acc[mi][ni][2];
            tile[(n_l + 1) * 132 + m_l + 8] = acc[mi][ni][3];
        }
    }
    __syncthreads();
    const int bb = m0 >> 16, cc = (m0 >> 8) & 255, h0 = m0 & 255;
#pragma unroll
    for (int itr = 0; itr < 32; itr++) {
        const int nl = warp + itr * 4;
        const float bj = __ldg(bias + n0 + nl);
        const uint64_t bjp = pack2(bj, bj);
        size_t base = ((size_t)bb << 24) + ((size_t)(n0 + nl) << 16)
                    + ((size_t)cc << 8) + (size_t)h0 + (size_t)(lane * 4);
        float4 tv = *(float4*)&tile[nl * 132 + lane * 4];
        float4 xv = *(const float4*)&xres[base];
        uint64_t* tp = (uint64_t*)&tv;
        const uint64_t* xp = (const uint64_t*)&xv;
        tp[0] = add2(add2(tp[0], bjp), xp[0]);
        tp[1] = add2(add2(tp[1], bjp), xp[1]);
        *(float4*)&C[base] = tv;
    }
}

// ---------------------------------------------------------------------------
extern "C" void kernel_launch(void* const* d_in, const int* in_sizes, int n_in,
                              void* d_out, int out_size)
{
    (void)in_sizes; (void)n_in; (void)out_size;
    const float* x   = (const float*)d_in[0];
    const float* cw  = (const float*)d_in[1];
    const float* cb  = (const float*)d_in[2];
    const float* g   = (const float*)d_in[3];
    const float* bta = (const float*)d_in[4];
    const float* w1  = (const float*)d_in[5];
    const float* b1  = (const float*)d_in[6];
    const float* w2  = (const float*)d_in[7];
    const float* b2  = (const float*)d_in[8];
    float* out = (float*)d_out;

    __nv_bfloat16 *Y, *H, *W1, *W2;
    cudaGetSymbolAddress((void**)&Y,  g_Y);
    cudaGetSymbolAddress((void**)&H,  g_H);
    cudaGetSymbolAddress((void**)&W1, g_W1);
    cudaGetSymbolAddress((void**)&W2, g_W2);

    const int SMEM_G1 = 114688;  // 64KB panel + 3 x 16KB A stages
    const int SMEM_G2 = 98304;   // 3 x 32KB stages (>= 67.6KB transpose tile)
    cudaFuncSetAttribute(gemm1_persist,
                         cudaFuncAttributeMaxDynamicSharedMemorySize, SMEM_G1);
    cudaFuncSetAttribute(gemm2_bf16,
                         cudaFuncAttributeMaxDynamicSharedMemorySize, SMEM_G2);

    // 1) conv + LN -> Y (16-row tiles), with weight prep fused on z==2 slice
    conv_ln_prep_kernel<<<dim3(DIM / 16, DIM, BATCH + 1), 128>>>(
        x, cw, cb, g, bta, Y, w1, w2, W1, W2);

    // 2) GEMM1 persistent + fast GELU -> H (bf16 tile-blocks)
    gemm1_persist<<<296, 128, SMEM_G1>>>(Y, W1, b1, H);

    // 3) GEMM2 + bias + transposed residual -> out (fp32)
    gemm2_bf16<<<dim3(2, M_ROWS / 128), 128, SMEM_G2>>>(H, W2, b2, x, out);
}